// round 12
// baseline (speedup 1.0000x reference)
#include <cuda_runtime.h>
#include <math.h>

// ---------------------------------------------------------------------------
// Problem constants
// ---------------------------------------------------------------------------
#define BB   8
#define NN_  512
#define MM   510
#define PP_  511
#define PI_F 3.14159265358979323846f

#define NNN   (NN_*NN_)
#define BNN   (BB*NNN)
#define MMM   (MM*MM)
#define BMM   (BB*MMM)

#define GD    512
#define GDD   (GD*GD)
#define BGDD  (BB*GDD)
#define BG2   (2*BGDD)

#define KH    256               // folded K
#define FQ    (KH*GD)           // one folded quad plane (256x512)

// conv buffer layout: halo'd planes, stride 520, 514 rows, domain at (+1,+4)
#define Z_W   520
#define Z_H   514
#define PLANE (Z_H*Z_W)
#define DOFF  (Z_W + 4)

// ---------------------------------------------------------------------------
// Static device scratch
// ---------------------------------------------------------------------------
__device__ float  d_x0[BNN];
__device__ float  d_x1[BNN];
__device__ float4 d_st4[BMM];
__device__ float d_Sf [GDD];
__device__ float d_SfT[GDD];
__device__ float d_Ce [GD*KH];        // [n, k] cos(pi*k*n/511), rows>=510 zero
__device__ float d_Se [GD*KH];
__device__ float d_CeT[KH*GD];        // [k, n], cols>=510 zero
__device__ float d_SeT[KH*GD];
__device__ float d_r1[BGDD];
__device__ float d_T1[BGDD];          // forward stage-1 temp
__device__ float d_rh[BB*PLANE];      // shared DST result (real)
__device__ float d_zar[16*4*PLANE];
__device__ float d_zai[16*4*PLANE];
__device__ float d_zbr[16*4*PLANE];
__device__ float d_zbi[16*4*PLANE];
__device__ float d_fold[16*4*FQ];     // per z: aE, bE, aO, bO  (K-major 256x512)
__device__ float d_m1[BG2];           // mA = Ce@aE
__device__ float d_m2[BG2];           // mB = Ce@bE
__device__ float d_m3[BG2];           // mC = Se@aO
__device__ float d_m4[BG2];           // mD = Se@bO
__device__ float d_PE[16*GD*KH];      // folded P, [m, k] lda=256
__device__ float d_QO[16*GD*KH];
__device__ float d_R[BG2];
__device__ double d_part[2*1024];

// ---------------------------------------------------------------------------
// Trig matrices
// ---------------------------------------------------------------------------
__global__ void trig_init_k()
{
    int x = blockIdx.x*blockDim.x + threadIdx.x;
    int y = blockIdx.y*blockDim.y + threadIdx.y;
    if (x >= GD || y >= GD) return;
    // forward DST matrix (padded 512x512)
    float sf = 0.f;
    if (y < PP_ && x < MM) {
        int t = (x+1) * (y-255);
        int m = t % 1022; if (m < 0) m += 1022;
        sf = sinf((float)m * (PI_F/511.0f));
    }
    d_Sf [y*GD + x] = sf;
    d_SfT[x*GD + y] = sf;
    // folded inverse matrices: k = x (<256), n = y (<510)
    if (x < KH) {
        float c = 0.f, s = 0.f;
        if (y < MM) {
            int m = (x * y) % 1022;
            float ang = (float)m * (PI_F/511.0f);
            c = cosf(ang); s = sinf(ang);
        }
        d_Ce [y*KH + x] = c;
        d_Se [y*KH + x] = s;
        d_CeT[x*GD + y] = c;
        d_SeT[x*GD + y] = s;
    }
}

// ---------------------------------------------------------------------------
// Stencil coefficients (precomputed, float4)
// ---------------------------------------------------------------------------
__global__ void stencil_k(const float* __restrict__ coef)
{
    int idx = blockIdx.x*blockDim.x + threadIdx.x;
    if (idx >= BMM) return;
    int i = idx % MM;
    int j = (idx / MM) % MM;
    int b = idx / MMM;
    const float* cb = coef + b*MMM;
    float a   = cb[j*MM + i];
    float aw  = cb[j*MM + (i>0    ? i-1 : 0   )];
    float ae  = cb[j*MM + (i<MM-1 ? i+1 : MM-1)];
    float an  = cb[(j<MM-1 ? j+1 : MM-1)*MM + i];
    float as_ = cb[(j>0    ? j-1 : 0   )*MM + i];
    float4 s;
    s.x = __fdividef(-2.f*aw *a, aw +a);
    s.y = __fdividef(-2.f*ae *a, ae +a);
    s.z = __fdividef(-2.f*an *a, an +a);
    s.w = __fdividef(-2.f*as_*a, as_+a);
    d_st4[idx] = s;
}

__device__ __forceinline__ float applyA(const float* __restrict__ xb, int b, int y, int x)
{
    int sidx = b*MMM + (y-1)*MM + (x-1);
    float4 s = d_st4[sidx];
    float sc = -(s.x + s.y + s.z + s.w);
    return s.w*xb[(y-1)*NN_+x] + s.x*xb[y*NN_+x-1] + sc*xb[y*NN_+x]
         + s.y*xb[y*NN_+x+1]   + s.z*xb[(y+1)*NN_+x];
}

__global__ void fill0_k(float* __restrict__ p, int n)
{
    int idx = blockIdx.x*blockDim.x + threadIdx.x;
    if (idx < n) p[idx] = 0.f;
}

__global__ void first_k(const float* __restrict__ f, float* __restrict__ xout, float w)
{
    int idx = blockIdx.x*blockDim.x + threadIdx.x;
    if (idx < BNN) xout[idx] = w*f[idx];
}

// zero halo cells of all conv-layout planes in one launch
__global__ void border_all_k(float* __restrict__ rh,
                             float* __restrict__ zar, float* __restrict__ zai,
                             float* __restrict__ zbr, float* __restrict__ zbi)
{
    int zb = blockIdx.x;
    float* pl;
    if (zb < 8) pl = rh + (size_t)zb * PLANE;
    else {
        int q = zb - 8;
        int buf = q >> 6;
        int p  = q & 63;
        float* base = (buf == 0) ? zar : (buf == 1) ? zai : (buf == 2) ? zbr : zbi;
        pl = base + (size_t)p * PLANE;
    }
    const int nA = 3*Z_W;
    const int nB = 511*9;
    for (int i = threadIdx.x; i < nA + nB; i += blockDim.x) {
        int off;
        if (i < nA) {
            int which = i / Z_W;
            int row = (which == 0) ? 0 : (which == 1 ? 512 : 513);
            off = row*Z_W + (i % Z_W);
        } else {
            int j = i - nA;
            int row = 1 + j/9;
            int c9 = j % 9;
            int col = (c9 < 4) ? c9 : (511 + c9);
            off = row*Z_W + col;
        }
        pl[off] = 0.f;
    }
}

// ---------------------------------------------------------------------------
// Fused 3-sweep Jacobi: 38x38 smem tile with shrinking windows 36->34->32.
// ---------------------------------------------------------------------------
__global__ __launch_bounds__(256) void jacobi3_k(
    const float* __restrict__ f, const float* __restrict__ xin,
    float* __restrict__ xout, float w)
{
    __shared__ float xs[2][38][39];
    __shared__ float fs[38][39];
    int tid = threadIdx.x;
    int gx0 = blockIdx.x*32 - 3;
    int gy0 = blockIdx.y*32 - 3;
    int b = blockIdx.z;
    const float* xb = xin + (size_t)b*NNN;
    const float* fb = f   + (size_t)b*NNN;

    for (int i = tid; i < 38*38; i += 256) {
        int ly = i / 38, lx = i % 38;
        int gy = gy0 + ly, gx = gx0 + lx;
        bool in = (gy >= 0 && gy < NN_ && gx >= 0 && gx < NN_);
        xs[0][ly][lx] = in ? xb[gy*NN_ + gx] : 0.f;
        fs[ly][lx]    = in ? fb[gy*NN_ + gx] : 0.f;
    }
    __syncthreads();

    int cur = 0;
    #pragma unroll
    for (int s = 0; s < 3; s++) {
        int m = s + 1;
        int W = 38 - 2*m;
        for (int i = tid; i < W*W; i += 256) {
            int ly = m + i / W, lx = m + i % W;
            int gy = gy0 + ly, gx = gx0 + lx;
            float xv = xs[cur][ly][lx];
            float out;
            if (gy < 0 || gy >= NN_ || gx < 0 || gx >= NN_) {
                out = 0.f;
            } else if (gy >= 1 && gy < NN_-1 && gx >= 1 && gx < NN_-1) {
                float4 st = d_st4[b*MMM + (gy-1)*MM + (gx-1)];
                float sc = -(st.x + st.y + st.z + st.w);
                float Ax = st.w*xs[cur][ly-1][lx] + st.x*xs[cur][ly][lx-1]
                         + sc*xv + st.y*xs[cur][ly][lx+1] + st.z*xs[cur][ly+1][lx];
                out = xv + w*(fs[ly][lx] - Ax);
            } else {
                out = xv + w*fs[ly][lx];
            }
            xs[cur^1][ly][lx] = out;
        }
        __syncthreads();
        cur ^= 1;
    }

    for (int i = tid; i < 32*32; i += 256) {
        int ly = 3 + i / 32, lx = 3 + i % 32;
        int gy = gy0 + ly, gx = gx0 + lx;
        xout[(size_t)b*NNN + gy*NN_ + gx] = xs[cur][ly][lx];
    }
}

__global__ void resid_k(const float* __restrict__ f, const float* __restrict__ xin)
{
    int idx = blockIdx.x*blockDim.x + threadIdx.x;
    if (idx >= BMM) return;
    int i = idx % MM;
    int j = (idx / MM) % MM;
    int b = idx / MMM;
    int y = j+1, x = i+1;
    d_r1[b*GDD + j*GD + i] = f[b*NNN + y*NN_ + x] - applyA(xin + b*NNN, b, y, x);
}

// ---------------------------------------------------------------------------
// helpers for packed f32x2
// ---------------------------------------------------------------------------
__device__ __forceinline__ unsigned long long splat2(float v)
{
    unsigned long long r;
    asm("mov.b64 %0, {%1, %1};" : "=l"(r) : "f"(v));
    return r;
}

// inner microkernel step shared by all GEMMs: 8x8 microtile from smem slices
__device__ __forceinline__ void mt_step(
    const float* __restrict__ Arow,   // &As[k][row], 16B aligned, 8 floats
    const float* __restrict__ Bcol,   // &Bs[k][col], 16B aligned, 8 floats
    unsigned long long (&acc)[8][4])
{
    float4 a01 = *(const float4*)(Arow);
    float4 a23 = *(const float4*)(Arow + 4);
    ulonglong2 bq0 = *(const ulonglong2*)(Bcol);
    ulonglong2 bq1 = *(const ulonglong2*)(Bcol + 4);
    unsigned long long b2[4] = {bq0.x, bq0.y, bq1.x, bq1.y};
    float a_[8] = {a01.x, a01.y, a01.z, a01.w, a23.x, a23.y, a23.z, a23.w};
    #pragma unroll
    for (int i = 0; i < 8; i++) {
        unsigned long long a2 = splat2(a_[i]);
        #pragma unroll
        for (int j = 0; j < 4; j++)
            asm("fma.rn.f32x2 %0, %1, %2, %0;"
                : "+l"(acc[i][j]) : "l"(a2), "l"(b2[j]));
    }
}

// ---------------------------------------------------------------------------
// 512^3 SGEMM, 128x128x8 tile, 8x8 microtile, ping-pong smem (1 barrier/blk)
// ---------------------------------------------------------------------------
__global__ __launch_bounds__(256, 2) void gemm512_k(
    const float* __restrict__ A, long long sA, int lda,
    const float* __restrict__ Bm, long long sB, int ldb,
    float* __restrict__ C, long long sC, int ldc,
    float alpha)
{
    const float* Ab = A  + blockIdx.z*sA;
    const float* Bb = Bm + blockIdx.z*sB;
    float*       Cb = C  + blockIdx.z*sC;
    __shared__ __align__(16) float As[2][8][132];
    __shared__ __align__(16) float Bs[2][8][128];
    int tid = threadIdx.x;
    int arow = tid >> 1;
    int acol = (tid & 1) << 2;
    int brow = tid >> 5;
    int bcol = (tid & 31) << 2;
    const int m0 = blockIdx.y * 128;
    const int n0 = blockIdx.x * 128;
    int row = (tid >> 4) << 3;
    int col = (tid & 15) << 3;

    unsigned long long acc[8][4];
    #pragma unroll
    for (int i = 0; i < 8; i++)
        #pragma unroll
        for (int j = 0; j < 4; j++) acc[i][j] = 0ull;

    const float* Aptr = Ab + (size_t)(m0+arow)*lda + acol;
    const float* Bptr = Bb + (size_t)brow*ldb + n0 + bcol;

    float4 av4 = *(const float4*)(Aptr);
    float4 bv4 = *(const float4*)(Bptr);
    int cur = 0;

    for (int k0 = 0; k0 < 512; k0 += 8) {
        As[cur][acol+0][arow] = av4.x;
        As[cur][acol+1][arow] = av4.y;
        As[cur][acol+2][arow] = av4.z;
        As[cur][acol+3][arow] = av4.w;
        *(float4*)&Bs[cur][brow][bcol] = bv4;
        __syncthreads();
        if (k0 + 8 < 512) {
            av4 = *(const float4*)(Aptr + (k0 + 8));
            bv4 = *(const float4*)(Bptr + (size_t)(k0 + 8)*ldb);
        }
        #pragma unroll
        for (int k = 0; k < 8; k++)
            mt_step(&As[cur][k][row], &Bs[cur][k][col], acc);
        cur ^= 1;
    }
    #pragma unroll
    for (int i = 0; i < 8; i++) {
        float* crow = Cb + (size_t)(m0+row+i)*ldc + n0 + col;
        #pragma unroll
        for (int j = 0; j < 4; j++) {
            float lo, hi;
            asm("mov.b64 {%0, %1}, %2;" : "=f"(lo), "=f"(hi) : "l"(acc[i][j]));
            float2 o; o.x = alpha*lo; o.y = alpha*hi;
            *(float2*)&crow[2*j] = o;
        }
    }
}

// ---------------------------------------------------------------------------
// Fold kernel: from z ch0 (a=Re, b=Im) build aE,bE,aO,bO (K=256 x 512), z=16
// ---------------------------------------------------------------------------
__global__ void foldz_k(const float* __restrict__ zr, const float* __restrict__ zi)
{
    int idx = blockIdx.x*blockDim.x + threadIdx.x;
    if (idx >= 16*FQ) return;
    int v  = idx % GD;
    int k  = (idx / GD) % KH;
    int zc = idx / FQ;
    const float* pa = zr + (size_t)zc*4*PLANE + DOFF;
    const float* pb = zi + (size_t)zc*4*PLANE + DOFF;
    float aE, bE, aO, bO;
    float ap = pa[(size_t)(255+k)*Z_W + v];
    float bp = pb[(size_t)(255+k)*Z_W + v];
    if (k == 0) {
        aE = ap; bE = bp; aO = 0.f; bO = 0.f;
    } else {
        float am = pa[(size_t)(255-k)*Z_W + v];
        float bm = pb[(size_t)(255-k)*Z_W + v];
        aE = ap + am; bE = bp + bm;
        aO = ap - am; bO = bp - bm;
    }
    size_t base = (size_t)zc*4*FQ + (size_t)k*GD + v;
    d_fold[base + 0*FQ] = aE;
    d_fold[base + 1*FQ] = bE;
    d_fold[base + 2*FQ] = aO;
    d_fold[base + 3*FQ] = bO;
}

// ---------------------------------------------------------------------------
// Quad GEMM (K=256), ping-pong: z in [0,64). sel = z>>4:
//   0: mA = Ce@aE   1: mB = Ce@bE   2: mC = Se@aO   3: mD = Se@bO
// ---------------------------------------------------------------------------
__global__ __launch_bounds__(256, 2) void gemm_quad_k(
    const float* __restrict__ Ce, const float* __restrict__ Se,
    float* __restrict__ m1, float* __restrict__ m2,
    float* __restrict__ m3, float* __restrict__ m4)
{
    int zz = blockIdx.z;
    int sel = zz >> 4;
    int zc  = zz & 15;
    const float* Ab = (sel < 2) ? Ce : Se;                     // lda = KH
    const float* Bb = d_fold + (size_t)(zc*4 + sel)*FQ;        // ldb = GD
    float* Cb = ((sel==0)?m1:(sel==1)?m2:(sel==2)?m3:m4) + (size_t)zc*GDD;

    __shared__ __align__(16) float As[2][8][132];
    __shared__ __align__(16) float Bs[2][8][128];
    int tid = threadIdx.x;
    int arow = tid >> 1;
    int acol = (tid & 1) << 2;
    int brow = tid >> 5;
    int bcol = (tid & 31) << 2;
    const int m0 = blockIdx.y * 128;
    const int n0 = blockIdx.x * 128;
    int row = (tid >> 4) << 3;
    int col = (tid & 15) << 3;

    unsigned long long acc[8][4];
    #pragma unroll
    for (int i = 0; i < 8; i++)
        #pragma unroll
        for (int j = 0; j < 4; j++) acc[i][j] = 0ull;

    const float* Aptr = Ab + (size_t)(m0+arow)*KH + acol;
    const float* Bptr = Bb + (size_t)brow*GD + n0 + bcol;

    float4 av4 = *(const float4*)(Aptr);
    float4 bv4 = *(const float4*)(Bptr);
    int cur = 0;

    for (int k0 = 0; k0 < KH; k0 += 8) {
        As[cur][acol+0][arow] = av4.x;
        As[cur][acol+1][arow] = av4.y;
        As[cur][acol+2][arow] = av4.z;
        As[cur][acol+3][arow] = av4.w;
        *(float4*)&Bs[cur][brow][bcol] = bv4;
        __syncthreads();
        if (k0 + 8 < KH) {
            av4 = *(const float4*)(Aptr + (k0 + 8));
            bv4 = *(const float4*)(Bptr + (size_t)(k0 + 8)*GD);
        }
        #pragma unroll
        for (int k = 0; k < 8; k++)
            mt_step(&As[cur][k][row], &Bs[cur][k][col], acc);
        cur ^= 1;
    }
    #pragma unroll
    for (int i = 0; i < 8; i++) {
        float* crow = Cb + (size_t)(m0+row+i)*GD + n0 + col;
        #pragma unroll
        for (int j = 0; j < 4; j++) {
            float lo, hi;
            asm("mov.b64 {%0, %1}, %2;" : "=f"(lo), "=f"(hi) : "l"(acc[i][j]));
            float2 o; o.x = lo; o.y = hi;
            *(float2*)&crow[2*j] = o;
        }
    }
}

// ---------------------------------------------------------------------------
// Combine + fold: P = mA+mD, Q = mB-mC; fold columns around 255.
// ---------------------------------------------------------------------------
__global__ void combine_fold_k()
{
    int idx = blockIdx.x*blockDim.x + threadIdx.x;
    if (idx >= 16*GD*KH) return;
    int k  = idx % KH;
    int m  = (idx / KH) % GD;
    int zc = idx / (GD*KH);
    size_t base = (size_t)zc*GDD + (size_t)m*GD;
    float PE, QO;
    float Pp = d_m1[base + 255 + k] + d_m4[base + 255 + k];
    if (k == 0) {
        PE = Pp;
        QO = 0.f;
    } else {
        float Pm = d_m1[base + 255 - k] + d_m4[base + 255 - k];
        PE = Pp + Pm;
        float Qp = d_m2[base + 255 + k] - d_m3[base + 255 + k];
        float Qm = d_m2[base + 255 - k] - d_m3[base + 255 - k];
        QO = Qp - Qm;
    }
    size_t o = (size_t)zc*GD*KH + (size_t)m*KH + k;
    d_PE[o] = PE;
    d_QO[o] = QO;
}

// ---------------------------------------------------------------------------
// Dual GEMM (K=256), ping-pong: R = PE@CeT + QO@SeT, z=16
// ---------------------------------------------------------------------------
__global__ __launch_bounds__(256, 2) void gemm_dualR_k(
    const float* __restrict__ PEm, const float* __restrict__ QOm,
    const float* __restrict__ B1, const float* __restrict__ B2,
    float* __restrict__ R)
{
    int zc = blockIdx.z;
    const float* Pb = PEm + (size_t)zc*GD*KH;
    const float* Qb = QOm + (size_t)zc*GD*KH;
    float* Cb = R + (size_t)zc*GDD;

    __shared__ __align__(16) float Ps[2][8][132];
    __shared__ __align__(16) float Qs[2][8][132];
    __shared__ __align__(16) float B1s[2][8][128];
    __shared__ __align__(16) float B2s[2][8][128];
    int tid = threadIdx.x;
    int arow = tid >> 1;
    int acol = (tid & 1) << 2;
    int brow = tid >> 5;
    int bcol = (tid & 31) << 2;
    const int m0 = blockIdx.y * 128;
    const int n0 = blockIdx.x * 128;
    int row = (tid >> 4) << 3;
    int col = (tid & 15) << 3;

    unsigned long long acc[8][4];
    #pragma unroll
    for (int i = 0; i < 8; i++)
        #pragma unroll
        for (int j = 0; j < 4; j++) acc[i][j] = 0ull;

    const float* Pptr = Pb + (size_t)(m0+arow)*KH + acol;
    const float* Qptr = Qb + (size_t)(m0+arow)*KH + acol;
    const float* B1p  = B1 + (size_t)brow*GD + n0 + bcol;
    const float* B2p  = B2 + (size_t)brow*GD + n0 + bcol;

    float4 pv  = *(const float4*)(Pptr);
    float4 qv  = *(const float4*)(Qptr);
    float4 b1v = *(const float4*)(B1p);
    float4 b2v = *(const float4*)(B2p);
    int cur = 0;

    for (int k0 = 0; k0 < KH; k0 += 8) {
        Ps[cur][acol+0][arow] = pv.x; Ps[cur][acol+1][arow] = pv.y;
        Ps[cur][acol+2][arow] = pv.z; Ps[cur][acol+3][arow] = pv.w;
        Qs[cur][acol+0][arow] = qv.x; Qs[cur][acol+1][arow] = qv.y;
        Qs[cur][acol+2][arow] = qv.z; Qs[cur][acol+3][arow] = qv.w;
        *(float4*)&B1s[cur][brow][bcol] = b1v;
        *(float4*)&B2s[cur][brow][bcol] = b2v;
        __syncthreads();
        if (k0 + 8 < KH) {
            pv  = *(const float4*)(Pptr + (k0 + 8));
            qv  = *(const float4*)(Qptr + (k0 + 8));
            b1v = *(const float4*)(B1p + (size_t)(k0 + 8)*GD);
            b2v = *(const float4*)(B2p + (size_t)(k0 + 8)*GD);
        }
        #pragma unroll
        for (int k = 0; k < 8; k++) {
            mt_step(&Ps[cur][k][row], &B1s[cur][k][col], acc);
            mt_step(&Qs[cur][k][row], &B2s[cur][k][col], acc);
        }
        cur ^= 1;
    }
    #pragma unroll
    for (int i = 0; i < 8; i++) {
        float* crow = Cb + (size_t)(m0+row+i)*GD + n0 + col;
        #pragma unroll
        for (int j = 0; j < 4; j++) {
            float lo, hi;
            asm("mov.b64 {%0, %1}, %2;" : "=f"(lo), "=f"(hi) : "l"(acc[i][j]));
            float2 o; o.x = lo; o.y = hi;
            *(float2*)&crow[2*j] = o;
        }
    }
}

// ---------------------------------------------------------------------------
// Tiled complex 3x3 conv with packed {Re,Im} fma.rn.f32x2 accumulation.
// ---------------------------------------------------------------------------
template<int CIN, int COUT, bool ADJ, bool REALIN, bool THETA>
__global__ __launch_bounds__(256) void conv_k(
    const float* __restrict__ xr, const float* __restrict__ xi,
    long long xbs, long long xcs, int in_bmask,
    const float* __restrict__ wr0, const float* __restrict__ wi0,
    const float* __restrict__ wr1, const float* __restrict__ wi1,
    float* __restrict__ yr, float* __restrict__ yi,
    const float* __restrict__ tr0, const float* __restrict__ ti0,
    const float* __restrict__ tr1, const float* __restrict__ ti1,
    int O0, int I0)
{
    const int NPL = CIN * (REALIN ? 1 : 2);
    __shared__ float sv[CIN*(REALIN?1:2)][34*34];
    __shared__ float2 swa[COUT*CIN*9];
    __shared__ float2 swb[COUT*CIN*9];

    int tid = threadIdx.y*32 + threadIdx.x;
    int zc = blockIdx.z;
    int b = zc & 7;
    int call = zc >> 3;
    int by = blockIdx.y, bx = blockIdx.x;

    const float* wr = call ? wr1 : wr0;
    const float* wi = call ? wi1 : wi0;

    for (int t = tid; t < COUT*CIN*9; t += 256) {
        int o = t / (CIN*9);
        int i = (t / 9) % CIN;
        int tap = t % 9;
        int dy = tap / 3, dx = tap % 3;
        int widx;
        float sgn;
        if (!ADJ) { widx = ((b*O0 + o)*I0 + i)*9 + dy*3 + dx; sgn = 1.f; }
        else      { widx = ((b*O0 + i)*I0 + o)*9 + dx*3 + dy; sgn = -1.f; }
        float wrv = wr[widx];
        float wiv = sgn * wi[widx];
        swa[t] = make_float2(wrv, wiv);
        swb[t] = make_float2(-wiv, wrv);
    }

    int ib = zc & in_bmask;
    for (int p = 0; p < NPL; p++) {
        int ch   = REALIN ? p : (p >> 1);
        bool im  = REALIN ? false : (p & 1);
        const float* src = (im ? xi : xr) + ib*xbs + ch*xcs;
        for (int idx = tid; idx < 34*34; idx += 256) {
            int r = idx / 34, c = idx % 34;
            int gy = by*32 + r - 1;
            int gxo = bx*32 + c + 3;
            sv[p][idx] = src[(size_t)(gy+1)*Z_W + gxo];
        }
    }
    __syncthreads();

    int tx = threadIdx.x;
    int r0 = threadIdx.y * 4;

    unsigned long long acc2[COUT][4];
    #pragma unroll
    for (int o = 0; o < COUT; o++)
        #pragma unroll
        for (int p = 0; p < 4; p++) acc2[o][p] = 0ull;

    #pragma unroll
    for (int i = 0; i < CIN; i++) {
        float vr[6][3], vi[6][3];
        #pragma unroll
        for (int ry = 0; ry < 6; ry++)
            #pragma unroll
            for (int cx = 0; cx < 3; cx++) {
                int sidx = (r0+ry)*34 + tx + cx;
                if (REALIN) { vr[ry][cx] = sv[i][sidx]; vi[ry][cx] = 0.f; }
                else        { vr[ry][cx] = sv[2*i][sidx]; vi[ry][cx] = sv[2*i+1][sidx]; }
            }
        #pragma unroll
        for (int dy = 0; dy < 3; dy++) {
            #pragma unroll
            for (int dx = 0; dx < 3; dx++) {
                unsigned long long wa[COUT], wb[COUT];
                #pragma unroll
                for (int o = 0; o < COUT; o++) {
                    wa[o] = *(const unsigned long long*)&swa[(o*CIN + i)*9 + dy*3 + dx];
                    if (!REALIN)
                        wb[o] = *(const unsigned long long*)&swb[(o*CIN + i)*9 + dy*3 + dx];
                }
                #pragma unroll
                for (int p = 0; p < 4; p++) {
                    unsigned long long a2 = splat2(vr[p+dy][dx]);
                    unsigned long long c2 = 0ull;
                    if (!REALIN) c2 = splat2(vi[p+dy][dx]);
                    #pragma unroll
                    for (int o = 0; o < COUT; o++) {
                        asm("fma.rn.f32x2 %0, %1, %2, %0;"
                            : "+l"(acc2[o][p]) : "l"(a2), "l"(wa[o]));
                        if (!REALIN)
                            asm("fma.rn.f32x2 %0, %1, %2, %0;"
                                : "+l"(acc2[o][p]) : "l"(c2), "l"(wb[o]));
                    }
                }
            }
        }
    }

    int gx = bx*32 + tx;
    if (gx >= PP_) return;
    #pragma unroll
    for (int p = 0; p < 4; p++) {
        int gy = by*32 + r0 + p;
        if (gy >= PP_) continue;
        size_t doff = (size_t)(gy+1)*Z_W + gx + 4;
        #pragma unroll
        for (int o = 0; o < COUT; o++) {
            float ar, ai;
            asm("mov.b64 {%0, %1}, %2;" : "=f"(ar), "=f"(ai) : "l"(acc2[o][p]));
            if (THETA) {
                const float* tr = call ? tr1 : tr0;
                const float* ti = call ? ti1 : ti0;
                float trv = tr[(size_t)b*PP_*PP_ + gy*PP_ + gx];
                float tiv = ti[(size_t)b*PP_*PP_ + gy*PP_ + gx];
                float nr = ar*trv - ai*tiv;
                float ni = ar*tiv + ai*trv;
                ar = nr; ai = ni;
            }
            yr[(size_t)(zc*4 + o)*PLANE + doff] = ar;
            yi[(size_t)(zc*4 + o)*PLANE + doff] = ai;
        }
    }
}

// x[interior] += coef<1 ? R[call0]/coef : R[call1]*coef
__global__ void update_x_k(float* __restrict__ x, const float* __restrict__ coef)
{
    int idx = blockIdx.x*blockDim.x + threadIdx.x;
    if (idx >= BMM) return;
    int i = idx % MM;
    int j = (idx / MM) % MM;
    int b = idx / MMM;
    float c = coef[idx];
    int ro = b*GDD + j*GD + i;
    float e = (c < 1.f) ? d_R[ro]/c : d_R[8*GDD + ro]*c;
    x[b*NNN + (j+1)*NN_ + (i+1)] += e;
}

// ---------------------------------------------------------------------------
// Final norms
// ---------------------------------------------------------------------------
__global__ void norm_partial_k(const float* __restrict__ f, const float* __restrict__ xin, int nblk)
{
    __shared__ double s1[256], s2[256];
    int tid = threadIdx.x;
    double ar = 0.0, af = 0.0;
    for (int idx = blockIdx.x*blockDim.x + tid; idx < BNN; idx += gridDim.x*blockDim.x) {
        int x = idx % NN_;
        int y = (idx / NN_) % NN_;
        int b = idx / NNN;
        float Ax = 0.f;
        if (y >= 1 && y < NN_-1 && x >= 1 && x < NN_-1)
            Ax = applyA(xin + b*NNN, b, y, x);
        float fv = f[idx];
        float r = fv - Ax;
        ar += (double)r*(double)r;
        af += (double)fv*(double)fv;
    }
    s1[tid] = ar; s2[tid] = af;
    __syncthreads();
    for (int s = 128; s > 0; s >>= 1) {
        if (tid < s) { s1[tid] += s1[tid+s]; s2[tid] += s2[tid+s]; }
        __syncthreads();
    }
    if (tid == 0) { d_part[blockIdx.x] = s1[0]; d_part[nblk + blockIdx.x] = s2[0]; }
}

__global__ void finalize_k(float* __restrict__ out, int nblk)
{
    __shared__ double s1[256], s2[256];
    int tid = threadIdx.x;
    double ar = 0.0, af = 0.0;
    for (int i = tid; i < nblk; i += 256) { ar += d_part[i]; af += d_part[nblk + i]; }
    s1[tid] = ar; s2[tid] = af;
    __syncthreads();
    for (int s = 128; s > 0; s >>= 1) {
        if (tid < s) { s1[tid] += s1[tid+s]; s2[tid] += s2[tid+s]; }
        __syncthreads();
    }
    if (tid == 0) out[0] = (float)sqrt(s1[0] / s2[0]);
}

// ---------------------------------------------------------------------------
// Host launch
// ---------------------------------------------------------------------------
extern "C" void kernel_launch(void* const* d_in, const int* in_sizes, int n_in,
                              void* d_out, int out_size)
{
    const float* f    = (const float*)d_in[0];
    const float* coef = (const float*)d_in[1];
    const float* w11r = (const float*)d_in[2];
    const float* w11i = (const float*)d_in[3];
    const float* w12r = (const float*)d_in[4];
    const float* w12i = (const float*)d_in[5];
    const float* w13r = (const float*)d_in[6];
    const float* w13i = (const float*)d_in[7];
    const float* t1r  = (const float*)d_in[8];
    const float* t1i  = (const float*)d_in[9];
    const float* w21r = (const float*)d_in[10];
    const float* w21i = (const float*)d_in[11];
    const float* w22r = (const float*)d_in[12];
    const float* w22i = (const float*)d_in[13];
    const float* w23r = (const float*)d_in[14];
    const float* w23i = (const float*)d_in[15];
    const float* t2r  = (const float*)d_in[16];
    const float* t2i  = (const float*)d_in[17];
    float* out = (float*)d_out;
    (void)in_sizes; (void)n_in; (void)out_size;

    float *p_x0, *p_x1, *p_r1, *p_T1, *p_rh;
    float *p_Sf, *p_SfT, *p_Ce, *p_Se, *p_CeT, *p_SeT;
    float *p_zar, *p_zai, *p_zbr, *p_zbi;
    float *p_m1, *p_m2, *p_m3, *p_m4, *p_PE, *p_QO, *p_R;
    cudaGetSymbolAddress((void**)&p_x0,  d_x0);
    cudaGetSymbolAddress((void**)&p_x1,  d_x1);
    cudaGetSymbolAddress((void**)&p_r1,  d_r1);
    cudaGetSymbolAddress((void**)&p_T1,  d_T1);
    cudaGetSymbolAddress((void**)&p_rh,  d_rh);
    cudaGetSymbolAddress((void**)&p_Sf,  d_Sf);
    cudaGetSymbolAddress((void**)&p_SfT, d_SfT);
    cudaGetSymbolAddress((void**)&p_Ce,  d_Ce);
    cudaGetSymbolAddress((void**)&p_Se,  d_Se);
    cudaGetSymbolAddress((void**)&p_CeT, d_CeT);
    cudaGetSymbolAddress((void**)&p_SeT, d_SeT);
    cudaGetSymbolAddress((void**)&p_zar, d_zar);
    cudaGetSymbolAddress((void**)&p_zai, d_zai);
    cudaGetSymbolAddress((void**)&p_zbr, d_zbr);
    cudaGetSymbolAddress((void**)&p_zbi, d_zbi);
    cudaGetSymbolAddress((void**)&p_m1,  d_m1);
    cudaGetSymbolAddress((void**)&p_m2,  d_m2);
    cudaGetSymbolAddress((void**)&p_m3,  d_m3);
    cudaGetSymbolAddress((void**)&p_m4,  d_m4);
    cudaGetSymbolAddress((void**)&p_PE,  d_PE);
    cudaGetSymbolAddress((void**)&p_QO,  d_QO);
    cudaGetSymbolAddress((void**)&p_R,   d_R);

    // init
    {
        dim3 b2(16,16), g2((GD+15)/16, (GD+15)/16);
        trig_init_k<<<g2, b2>>>();
    }
    stencil_k<<<(BMM+255)/256, 256>>>(coef);
    fill0_k<<<(BGDD+255)/256, 256>>>(p_r1, BGDD);
    border_all_k<<<8 + 4*64, 256>>>(p_rh, p_zar, p_zai, p_zbr, p_zbi);

    // 10 Jacobi updates from x=0 (epoch==1 -> K=1): x=w*f then 3 fused 3-sweeps
    const float wrelax = 40.0f / 512.0f;
    first_k<<<(BNN+255)/256, 256>>>(f, p_x0, wrelax);
    {
        dim3 jg(16,16,BB);
        jacobi3_k<<<jg, 256>>>(f, p_x0, p_x1, wrelax);
        jacobi3_k<<<jg, 256>>>(f, p_x1, p_x0, wrelax);
        jacobi3_k<<<jg, 256>>>(f, p_x0, p_x1, wrelax);
    }
    float* xa = p_x1;
    resid_k<<<(BMM+255)/256, 256>>>(f, xa);

    dim3 gg8(4,4,BB);
    // shared forward DST: rh = -(1/511^2) * Sf @ r1 @ SfT
    gemm512_k<<<gg8, 256>>>(p_Sf, 0, GD,  p_r1, GDD, GD,  p_T1, GDD, GD, 1.0f);
    gemm512_k<<<gg8, 256>>>(p_T1, GDD, GD, p_SfT, 0, GD,
                            p_rh + DOFF, (long long)PLANE, Z_W,
                            -1.0f/(511.0f*511.0f));

    // both conv chains, merged over z=16
    dim3 cg(16,16,16), cbk(32,8);
    long long cb_bs = 4LL*PLANE, cb_cs = PLANE;

    conv_k<1,4,false,true ,false><<<cg,cbk>>>(p_rh, nullptr, (long long)PLANE, 0, 7,
        w11r, w11i, w21r, w21i, p_zbr, p_zbi, nullptr,nullptr,nullptr,nullptr, 4, 1);
    conv_k<4,4,false,false,false><<<cg,cbk>>>(p_zbr, p_zbi, cb_bs, cb_cs, 15,
        w12r, w12i, w22r, w22i, p_zar, p_zai, nullptr,nullptr,nullptr,nullptr, 4, 4);
    conv_k<4,1,false,false,true ><<<cg,cbk>>>(p_zar, p_zai, cb_bs, cb_cs, 15,
        w13r, w13i, w23r, w23i, p_zbr, p_zbi, t1r, t1i, t2r, t2i, 1, 4);
    conv_k<1,4,true ,false,false><<<cg,cbk>>>(p_zbr, p_zbi, cb_bs, cb_cs, 15,
        w13r, w13i, w23r, w23i, p_zar, p_zai, nullptr,nullptr,nullptr,nullptr, 1, 4);
    conv_k<4,4,true ,false,false><<<cg,cbk>>>(p_zar, p_zai, cb_bs, cb_cs, 15,
        w12r, w12i, w22r, w22i, p_zbr, p_zbi, nullptr,nullptr,nullptr,nullptr, 4, 4);
    conv_k<4,1,true ,false,false><<<cg,cbk>>>(p_zbr, p_zbi, cb_bs, cb_cs, 15,
        w11r, w11i, w21r, w21i, p_zar, p_zai, nullptr,nullptr,nullptr,nullptr, 4, 1);

    // inverse via parity folding: K=256 GEMMs
    foldz_k<<<(16*FQ + 255)/256, 256>>>(p_zar, p_zai);
    {
        dim3 gq(4,4,64);
        gemm_quad_k<<<gq,256>>>(p_Ce, p_Se, p_m1, p_m2, p_m3, p_m4);
    }
    combine_fold_k<<<(16*GD*KH + 255)/256, 256>>>();
    {
        dim3 gdr(4,4,16);
        gemm_dualR_k<<<gdr,256>>>(p_PE, p_QO, p_CeT, p_SeT, p_R);
    }

    update_x_k<<<(BMM+255)/256, 256>>>(xa, coef);
    const int nblk = 1024;
    norm_partial_k<<<nblk, 256>>>(f, xa, nblk);
    finalize_k<<<1, 256>>>(out, nblk);
}

// round 13
// speedup vs baseline: 1.0189x; 1.0189x over previous
#include <cuda_runtime.h>
#include <math.h>

// ---------------------------------------------------------------------------
// Problem constants
// ---------------------------------------------------------------------------
#define BB   8
#define NN_  512
#define MM   510
#define PP_  511
#define PI_F 3.14159265358979323846f

#define NNN   (NN_*NN_)
#define BNN   (BB*NNN)
#define MMM   (MM*MM)
#define BMM   (BB*MMM)

#define GD    512
#define GDD   (GD*GD)
#define BGDD  (BB*GDD)
#define BG2   (2*BGDD)

#define KH    256               // folded K
#define FQ    (KH*GD)           // one folded quad plane (256x512)

// conv buffer layout: halo'd planes, stride 520, 514 rows, domain at (+1,+4)
#define Z_W   520
#define Z_H   514
#define PLANE (Z_H*Z_W)
#define DOFF  (Z_W + 4)

// ---------------------------------------------------------------------------
// Static device scratch
// ---------------------------------------------------------------------------
__device__ float  d_x0[BNN];
__device__ float  d_x1[BNN];
__device__ float4 d_st4[BMM];
__device__ float d_Sf [GDD];
__device__ float d_SfT[GDD];
__device__ float d_Ce [GD*KH];        // [n, k] cos(pi*k*n/511), rows>=510 zero
__device__ float d_Se [GD*KH];
__device__ float d_CeT[KH*GD];        // [k, n], cols>=510 zero
__device__ float d_SeT[KH*GD];
__device__ float d_r1[BGDD];          // zero-init; pad cells kept zero by r1pad_k
__device__ float d_T1[BGDD];          // forward stage-1 temp
__device__ float d_rh[BB*PLANE];      // shared DST result (real)
__device__ float d_zar[16*4*PLANE];
__device__ float d_zai[16*4*PLANE];
__device__ float d_zbr[16*4*PLANE];
__device__ float d_zbi[16*4*PLANE];
__device__ float d_fold[16*4*FQ];     // per z: aE, bE, aO, bO  (K-major 256x512)
__device__ float d_m1[BG2];           // mA = Ce@aE
__device__ float d_m2[BG2];           // mB = Ce@bE
__device__ float d_m3[BG2];           // mC = Se@aO
__device__ float d_m4[BG2];           // mD = Se@bO
__device__ float d_PE[16*GD*KH];      // folded P, [m, k] lda=256
__device__ float d_QO[16*GD*KH];
__device__ float d_R[BG2];
__device__ double d_part[2*1024];

// ---------------------------------------------------------------------------
// Trig matrices
// ---------------------------------------------------------------------------
__global__ void trig_init_k()
{
    int x = blockIdx.x*blockDim.x + threadIdx.x;
    int y = blockIdx.y*blockDim.y + threadIdx.y;
    if (x >= GD || y >= GD) return;
    // forward DST matrix (padded 512x512)
    float sf = 0.f;
    if (y < PP_ && x < MM) {
        int t = (x+1) * (y-255);
        int m = t % 1022; if (m < 0) m += 1022;
        sf = sinf((float)m * (PI_F/511.0f));
    }
    d_Sf [y*GD + x] = sf;
    d_SfT[x*GD + y] = sf;
    // folded inverse matrices: k = x (<256), n = y (<510)
    if (x < KH) {
        float c = 0.f, s = 0.f;
        if (y < MM) {
            int m = (x * y) % 1022;
            float ang = (float)m * (PI_F/511.0f);
            c = cosf(ang); s = sinf(ang);
        }
        d_Ce [y*KH + x] = c;
        d_Se [y*KH + x] = s;
        d_CeT[x*GD + y] = c;
        d_SeT[x*GD + y] = s;
    }
}

// ---------------------------------------------------------------------------
// Stencil coefficients (precomputed, float4)
// ---------------------------------------------------------------------------
__global__ void stencil_k(const float* __restrict__ coef)
{
    int idx = blockIdx.x*blockDim.x + threadIdx.x;
    if (idx >= BMM) return;
    int i = idx % MM;
    int j = (idx / MM) % MM;
    int b = idx / MMM;
    const float* cb = coef + b*MMM;
    float a   = cb[j*MM + i];
    float aw  = cb[j*MM + (i>0    ? i-1 : 0   )];
    float ae  = cb[j*MM + (i<MM-1 ? i+1 : MM-1)];
    float an  = cb[(j<MM-1 ? j+1 : MM-1)*MM + i];
    float as_ = cb[(j>0    ? j-1 : 0   )*MM + i];
    float4 s;
    s.x = __fdividef(-2.f*aw *a, aw +a);
    s.y = __fdividef(-2.f*ae *a, ae +a);
    s.z = __fdividef(-2.f*an *a, an +a);
    s.w = __fdividef(-2.f*as_*a, as_+a);
    d_st4[idx] = s;
}

__device__ __forceinline__ float applyA(const float* __restrict__ xb, int b, int y, int x)
{
    int sidx = b*MMM + (y-1)*MM + (x-1);
    float4 s = d_st4[sidx];
    float sc = -(s.x + s.y + s.z + s.w);
    return s.w*xb[(y-1)*NN_+x] + s.x*xb[y*NN_+x-1] + sc*xb[y*NN_+x]
         + s.y*xb[y*NN_+x+1]   + s.z*xb[(y+1)*NN_+x];
}

// zero only the pad cells of r1 (rows/cols >= 510); interior rewritten by resid_k
__global__ void r1pad_k()
{
    int b = blockIdx.x;
    float* p = d_r1 + (size_t)b*GDD;
    for (int t = threadIdx.x; t < 2044; t += 256) {
        int off;
        if (t < 1024) {
            int j = 510 + (t >> 9);
            int i = t & 511;
            off = j*GD + i;
        } else {
            int q = t - 1024;
            int j = q >> 1;
            int i = 510 + (q & 1);
            off = j*GD + i;
        }
        p[off] = 0.f;
    }
}

__global__ void first_k(const float* __restrict__ f, float* __restrict__ xout, float w)
{
    int idx = blockIdx.x*blockDim.x + threadIdx.x;
    if (idx < BNN) xout[idx] = w*f[idx];
}

// zero halo cells of all conv-layout planes in one launch
__global__ void border_all_k(float* __restrict__ rh,
                             float* __restrict__ zar, float* __restrict__ zai,
                             float* __restrict__ zbr, float* __restrict__ zbi)
{
    int zb = blockIdx.x;
    float* pl;
    if (zb < 8) pl = rh + (size_t)zb * PLANE;
    else {
        int q = zb - 8;
        int buf = q >> 6;
        int p  = q & 63;
        float* base = (buf == 0) ? zar : (buf == 1) ? zai : (buf == 2) ? zbr : zbi;
        pl = base + (size_t)p * PLANE;
    }
    const int nA = 3*Z_W;
    const int nB = 511*9;
    for (int i = threadIdx.x; i < nA + nB; i += blockDim.x) {
        int off;
        if (i < nA) {
            int which = i / Z_W;
            int row = (which == 0) ? 0 : (which == 1 ? 512 : 513);
            off = row*Z_W + (i % Z_W);
        } else {
            int j = i - nA;
            int row = 1 + j/9;
            int c9 = j % 9;
            int col = (c9 < 4) ? c9 : (511 + c9);
            off = row*Z_W + col;
        }
        pl[off] = 0.f;
    }
}

// ---------------------------------------------------------------------------
// Fused 3-sweep Jacobi: 38x38 smem tile with shrinking windows 36->34->32.
// ---------------------------------------------------------------------------
__global__ __launch_bounds__(256) void jacobi3_k(
    const float* __restrict__ f, const float* __restrict__ xin,
    float* __restrict__ xout, float w)
{
    __shared__ float xs[2][38][39];
    __shared__ float fs[38][39];
    int tid = threadIdx.x;
    int gx0 = blockIdx.x*32 - 3;
    int gy0 = blockIdx.y*32 - 3;
    int b = blockIdx.z;
    const float* xb = xin + (size_t)b*NNN;
    const float* fb = f   + (size_t)b*NNN;

    for (int i = tid; i < 38*38; i += 256) {
        int ly = i / 38, lx = i % 38;
        int gy = gy0 + ly, gx = gx0 + lx;
        bool in = (gy >= 0 && gy < NN_ && gx >= 0 && gx < NN_);
        xs[0][ly][lx] = in ? xb[gy*NN_ + gx] : 0.f;
        fs[ly][lx]    = in ? fb[gy*NN_ + gx] : 0.f;
    }
    __syncthreads();

    int cur = 0;
    #pragma unroll
    for (int s = 0; s < 3; s++) {
        int m = s + 1;
        int W = 38 - 2*m;
        for (int i = tid; i < W*W; i += 256) {
            int ly = m + i / W, lx = m + i % W;
            int gy = gy0 + ly, gx = gx0 + lx;
            float xv = xs[cur][ly][lx];
            float out;
            if (gy < 0 || gy >= NN_ || gx < 0 || gx >= NN_) {
                out = 0.f;
            } else if (gy >= 1 && gy < NN_-1 && gx >= 1 && gx < NN_-1) {
                float4 st = d_st4[b*MMM + (gy-1)*MM + (gx-1)];
                float sc = -(st.x + st.y + st.z + st.w);
                float Ax = st.w*xs[cur][ly-1][lx] + st.x*xs[cur][ly][lx-1]
                         + sc*xv + st.y*xs[cur][ly][lx+1] + st.z*xs[cur][ly+1][lx];
                out = xv + w*(fs[ly][lx] - Ax);
            } else {
                out = xv + w*fs[ly][lx];
            }
            xs[cur^1][ly][lx] = out;
        }
        __syncthreads();
        cur ^= 1;
    }

    for (int i = tid; i < 32*32; i += 256) {
        int ly = 3 + i / 32, lx = 3 + i % 32;
        int gy = gy0 + ly, gx = gx0 + lx;
        xout[(size_t)b*NNN + gy*NN_ + gx] = xs[cur][ly][lx];
    }
}

__global__ void resid_k(const float* __restrict__ f, const float* __restrict__ xin)
{
    int idx = blockIdx.x*blockDim.x + threadIdx.x;
    if (idx >= BMM) return;
    int i = idx % MM;
    int j = (idx / MM) % MM;
    int b = idx / MMM;
    int y = j+1, x = i+1;
    d_r1[b*GDD + j*GD + i] = f[b*NNN + y*NN_ + x] - applyA(xin + b*NNN, b, y, x);
}

// ---------------------------------------------------------------------------
// helpers for packed f32x2
// ---------------------------------------------------------------------------
__device__ __forceinline__ unsigned long long splat2(float v)
{
    unsigned long long r;
    asm("mov.b64 %0, {%1, %1};" : "=l"(r) : "f"(v));
    return r;
}

// ---------------------------------------------------------------------------
// 512^3 SGEMM, 128x128x8 tile, 8x8 microtile, scalar-A + reg splat (proven core)
// ---------------------------------------------------------------------------
__global__ __launch_bounds__(256, 2) void gemm512_k(
    const float* __restrict__ A, long long sA, int lda,
    const float* __restrict__ Bm, long long sB, int ldb,
    float* __restrict__ C, long long sC, int ldc,
    float alpha)
{
    const float* Ab = A  + blockIdx.z*sA;
    const float* Bb = Bm + blockIdx.z*sB;
    float*       Cb = C  + blockIdx.z*sC;
    __shared__ float As[8][132];
    __shared__ float Bs[8][128];
    int tid = threadIdx.x;
    int arow = tid >> 1;
    int acol = (tid & 1) << 2;
    int brow = tid >> 5;
    int bcol = (tid & 31) << 2;
    const int m0 = blockIdx.y * 128;
    const int n0 = blockIdx.x * 128;
    int row = (tid >> 4) << 3;
    int col = (tid & 15) << 3;

    unsigned long long acc[8][4];
    #pragma unroll
    for (int i = 0; i < 8; i++)
        #pragma unroll
        for (int j = 0; j < 4; j++) acc[i][j] = 0ull;

    const float* Aptr = Ab + (size_t)(m0+arow)*lda + acol;
    const float* Bptr = Bb + (size_t)brow*ldb + n0 + bcol;

    float4 av4 = *(const float4*)(Aptr);
    float4 bv4 = *(const float4*)(Bptr);

    for (int k0 = 0; k0 < 512; k0 += 8) {
        As[acol+0][arow] = av4.x;
        As[acol+1][arow] = av4.y;
        As[acol+2][arow] = av4.z;
        As[acol+3][arow] = av4.w;
        *(float4*)&Bs[brow][bcol] = bv4;
        __syncthreads();
        if (k0 + 8 < 512) {
            av4 = *(const float4*)(Aptr + (k0 + 8));
            bv4 = *(const float4*)(Bptr + (size_t)(k0 + 8)*ldb);
        }
        #pragma unroll
        for (int k = 0; k < 8; k++) {
            float a_[8];
            #pragma unroll
            for (int i = 0; i < 4; i++) {
                float2 t = *(const float2*)&As[k][row + 2*i];
                a_[2*i] = t.x; a_[2*i+1] = t.y;
            }
            unsigned long long b2[4];
            #pragma unroll
            for (int j = 0; j < 4; j++)
                b2[j] = *(const unsigned long long*)&Bs[k][col + 2*j];
            #pragma unroll
            for (int i = 0; i < 8; i++) {
                unsigned long long a2 = splat2(a_[i]);
                #pragma unroll
                for (int j = 0; j < 4; j++)
                    asm("fma.rn.f32x2 %0, %1, %2, %0;"
                        : "+l"(acc[i][j]) : "l"(a2), "l"(b2[j]));
            }
        }
        __syncthreads();
    }
    #pragma unroll
    for (int i = 0; i < 8; i++) {
        float* crow = Cb + (size_t)(m0+row+i)*ldc + n0 + col;
        #pragma unroll
        for (int j = 0; j < 4; j++) {
            float lo, hi;
            asm("mov.b64 {%0, %1}, %2;" : "=f"(lo), "=f"(hi) : "l"(acc[i][j]));
            float2 o; o.x = alpha*lo; o.y = alpha*hi;
            *(float2*)&crow[2*j] = o;
        }
    }
}

// ---------------------------------------------------------------------------
// Fold kernel: from z ch0 (a=Re, b=Im) build aE,bE,aO,bO (K=256 x 512), z=16
// ---------------------------------------------------------------------------
__global__ void foldz_k(const float* __restrict__ zr, const float* __restrict__ zi)
{
    int idx = blockIdx.x*blockDim.x + threadIdx.x;
    if (idx >= 16*FQ) return;
    int v  = idx % GD;
    int k  = (idx / GD) % KH;
    int zc = idx / FQ;
    const float* pa = zr + (size_t)zc*4*PLANE + DOFF;
    const float* pb = zi + (size_t)zc*4*PLANE + DOFF;
    float aE, bE, aO, bO;
    float ap = pa[(size_t)(255+k)*Z_W + v];
    float bp = pb[(size_t)(255+k)*Z_W + v];
    if (k == 0) {
        aE = ap; bE = bp; aO = 0.f; bO = 0.f;
    } else {
        float am = pa[(size_t)(255-k)*Z_W + v];
        float bm = pb[(size_t)(255-k)*Z_W + v];
        aE = ap + am; bE = bp + bm;
        aO = ap - am; bO = bp - bm;
    }
    size_t base = (size_t)zc*4*FQ + (size_t)k*GD + v;
    d_fold[base + 0*FQ] = aE;
    d_fold[base + 1*FQ] = bE;
    d_fold[base + 2*FQ] = aO;
    d_fold[base + 3*FQ] = bO;
}

// ---------------------------------------------------------------------------
// Quad GEMM (K=256): z in [0,64). sel = z>>4:
//   0: mA = Ce@aE   1: mB = Ce@bE   2: mC = Se@aO   3: mD = Se@bO
// ---------------------------------------------------------------------------
__global__ __launch_bounds__(256, 2) void gemm_quad_k(
    const float* __restrict__ Ce, const float* __restrict__ Se,
    float* __restrict__ m1, float* __restrict__ m2,
    float* __restrict__ m3, float* __restrict__ m4)
{
    int zz = blockIdx.z;
    int sel = zz >> 4;
    int zc  = zz & 15;
    const float* Ab = (sel < 2) ? Ce : Se;                     // lda = KH
    const float* Bb = d_fold + (size_t)(zc*4 + sel)*FQ;        // ldb = GD
    float* Cb = ((sel==0)?m1:(sel==1)?m2:(sel==2)?m3:m4) + (size_t)zc*GDD;

    __shared__ float As[8][132];
    __shared__ float Bs[8][128];
    int tid = threadIdx.x;
    int arow = tid >> 1;
    int acol = (tid & 1) << 2;
    int brow = tid >> 5;
    int bcol = (tid & 31) << 2;
    const int m0 = blockIdx.y * 128;
    const int n0 = blockIdx.x * 128;
    int row = (tid >> 4) << 3;
    int col = (tid & 15) << 3;

    unsigned long long acc[8][4];
    #pragma unroll
    for (int i = 0; i < 8; i++)
        #pragma unroll
        for (int j = 0; j < 4; j++) acc[i][j] = 0ull;

    const float* Aptr = Ab + (size_t)(m0+arow)*KH + acol;
    const float* Bptr = Bb + (size_t)brow*GD + n0 + bcol;

    float4 av4 = *(const float4*)(Aptr);
    float4 bv4 = *(const float4*)(Bptr);

    for (int k0 = 0; k0 < KH; k0 += 8) {
        As[acol+0][arow] = av4.x;
        As[acol+1][arow] = av4.y;
        As[acol+2][arow] = av4.z;
        As[acol+3][arow] = av4.w;
        *(float4*)&Bs[brow][bcol] = bv4;
        __syncthreads();
        if (k0 + 8 < KH) {
            av4 = *(const float4*)(Aptr + (k0 + 8));
            bv4 = *(const float4*)(Bptr + (size_t)(k0 + 8)*GD);
        }
        #pragma unroll
        for (int k = 0; k < 8; k++) {
            float a_[8];
            #pragma unroll
            for (int i = 0; i < 4; i++) {
                float2 t = *(const float2*)&As[k][row + 2*i];
                a_[2*i] = t.x; a_[2*i+1] = t.y;
            }
            unsigned long long b2[4];
            #pragma unroll
            for (int j = 0; j < 4; j++)
                b2[j] = *(const unsigned long long*)&Bs[k][col + 2*j];
            #pragma unroll
            for (int i = 0; i < 8; i++) {
                unsigned long long a2 = splat2(a_[i]);
                #pragma unroll
                for (int j = 0; j < 4; j++)
                    asm("fma.rn.f32x2 %0, %1, %2, %0;"
                        : "+l"(acc[i][j]) : "l"(a2), "l"(b2[j]));
            }
        }
        __syncthreads();
    }
    #pragma unroll
    for (int i = 0; i < 8; i++) {
        float* crow = Cb + (size_t)(m0+row+i)*GD + n0 + col;
        #pragma unroll
        for (int j = 0; j < 4; j++) {
            float lo, hi;
            asm("mov.b64 {%0, %1}, %2;" : "=f"(lo), "=f"(hi) : "l"(acc[i][j]));
            float2 o; o.x = lo; o.y = hi;
            *(float2*)&crow[2*j] = o;
        }
    }
}

// ---------------------------------------------------------------------------
// Combine + fold: P = mA+mD, Q = mB-mC; fold columns around 255.
// ---------------------------------------------------------------------------
__global__ void combine_fold_k()
{
    int idx = blockIdx.x*blockDim.x + threadIdx.x;
    if (idx >= 16*GD*KH) return;
    int k  = idx % KH;
    int m  = (idx / KH) % GD;
    int zc = idx / (GD*KH);
    size_t base = (size_t)zc*GDD + (size_t)m*GD;
    float PE, QO;
    float Pp = d_m1[base + 255 + k] + d_m4[base + 255 + k];
    if (k == 0) {
        PE = Pp;
        QO = 0.f;
    } else {
        float Pm = d_m1[base + 255 - k] + d_m4[base + 255 - k];
        PE = Pp + Pm;
        float Qp = d_m2[base + 255 + k] - d_m3[base + 255 + k];
        float Qm = d_m2[base + 255 - k] - d_m3[base + 255 - k];
        QO = Qp - Qm;
    }
    size_t o = (size_t)zc*GD*KH + (size_t)m*KH + k;
    d_PE[o] = PE;
    d_QO[o] = QO;
}

// ---------------------------------------------------------------------------
// Dual GEMM (K=256): R = PE@CeT + QO@SeT, z=16
// ---------------------------------------------------------------------------
__global__ __launch_bounds__(256, 2) void gemm_dualR_k(
    const float* __restrict__ PEm, const float* __restrict__ QOm,
    const float* __restrict__ B1, const float* __restrict__ B2,
    float* __restrict__ R)
{
    int zc = blockIdx.z;
    const float* Pb = PEm + (size_t)zc*GD*KH;
    const float* Qb = QOm + (size_t)zc*GD*KH;
    float* Cb = R + (size_t)zc*GDD;

    __shared__ float Ps[8][132];
    __shared__ float Qs[8][132];
    __shared__ float B1s[8][128];
    __shared__ float B2s[8][128];
    int tid = threadIdx.x;
    int arow = tid >> 1;
    int acol = (tid & 1) << 2;
    int brow = tid >> 5;
    int bcol = (tid & 31) << 2;
    const int m0 = blockIdx.y * 128;
    const int n0 = blockIdx.x * 128;
    int row = (tid >> 4) << 3;
    int col = (tid & 15) << 3;

    unsigned long long acc[8][4];
    #pragma unroll
    for (int i = 0; i < 8; i++)
        #pragma unroll
        for (int j = 0; j < 4; j++) acc[i][j] = 0ull;

    const float* Pptr = Pb + (size_t)(m0+arow)*KH + acol;
    const float* Qptr = Qb + (size_t)(m0+arow)*KH + acol;
    const float* B1p  = B1 + (size_t)brow*GD + n0 + bcol;
    const float* B2p  = B2 + (size_t)brow*GD + n0 + bcol;

    float4 pv  = *(const float4*)(Pptr);
    float4 qv  = *(const float4*)(Qptr);
    float4 b1v = *(const float4*)(B1p);
    float4 b2v = *(const float4*)(B2p);

    for (int k0 = 0; k0 < KH; k0 += 8) {
        Ps[acol+0][arow] = pv.x; Ps[acol+1][arow] = pv.y;
        Ps[acol+2][arow] = pv.z; Ps[acol+3][arow] = pv.w;
        Qs[acol+0][arow] = qv.x; Qs[acol+1][arow] = qv.y;
        Qs[acol+2][arow] = qv.z; Qs[acol+3][arow] = qv.w;
        *(float4*)&B1s[brow][bcol] = b1v;
        *(float4*)&B2s[brow][bcol] = b2v;
        __syncthreads();
        if (k0 + 8 < KH) {
            pv  = *(const float4*)(Pptr + (k0 + 8));
            qv  = *(const float4*)(Qptr + (k0 + 8));
            b1v = *(const float4*)(B1p + (size_t)(k0 + 8)*GD);
            b2v = *(const float4*)(B2p + (size_t)(k0 + 8)*GD);
        }
        #pragma unroll
        for (int k = 0; k < 8; k++) {
            float ap[8], aq[8];
            #pragma unroll
            for (int i = 0; i < 4; i++) {
                float2 t1 = *(const float2*)&Ps[k][row + 2*i];
                float2 t2 = *(const float2*)&Qs[k][row + 2*i];
                ap[2*i] = t1.x; ap[2*i+1] = t1.y;
                aq[2*i] = t2.x; aq[2*i+1] = t2.y;
            }
            unsigned long long c2[4], s2[4];
            #pragma unroll
            for (int j = 0; j < 4; j++) {
                c2[j] = *(const unsigned long long*)&B1s[k][col + 2*j];
                s2[j] = *(const unsigned long long*)&B2s[k][col + 2*j];
            }
            #pragma unroll
            for (int i = 0; i < 8; i++) {
                unsigned long long a2p = splat2(ap[i]);
                unsigned long long a2q = splat2(aq[i]);
                #pragma unroll
                for (int j = 0; j < 4; j++) {
                    asm("fma.rn.f32x2 %0, %1, %2, %0;"
                        : "+l"(acc[i][j]) : "l"(a2p), "l"(c2[j]));
                    asm("fma.rn.f32x2 %0, %1, %2, %0;"
                        : "+l"(acc[i][j]) : "l"(a2q), "l"(s2[j]));
                }
            }
        }
        __syncthreads();
    }
    #pragma unroll
    for (int i = 0; i < 8; i++) {
        float* crow = Cb + (size_t)(m0+row+i)*GD + n0 + col;
        #pragma unroll
        for (int j = 0; j < 4; j++) {
            float lo, hi;
            asm("mov.b64 {%0, %1}, %2;" : "=f"(lo), "=f"(hi) : "l"(acc[i][j]));
            float2 o; o.x = lo; o.y = hi;
            *(float2*)&crow[2*j] = o;
        }
    }
}

// ---------------------------------------------------------------------------
// Tiled complex 3x3 conv with packed {Re,Im} fma.rn.f32x2 accumulation.
// ---------------------------------------------------------------------------
template<int CIN, int COUT, bool ADJ, bool REALIN, bool THETA>
__global__ __launch_bounds__(256) void conv_k(
    const float* __restrict__ xr, const float* __restrict__ xi,
    long long xbs, long long xcs, int in_bmask,
    const float* __restrict__ wr0, const float* __restrict__ wi0,
    const float* __restrict__ wr1, const float* __restrict__ wi1,
    float* __restrict__ yr, float* __restrict__ yi,
    const float* __restrict__ tr0, const float* __restrict__ ti0,
    const float* __restrict__ tr1, const float* __restrict__ ti1,
    int O0, int I0)
{
    const int NPL = CIN * (REALIN ? 1 : 2);
    __shared__ float sv[CIN*(REALIN?1:2)][34*34];
    __shared__ float2 swa[COUT*CIN*9];
    __shared__ float2 swb[COUT*CIN*9];

    int tid = threadIdx.y*32 + threadIdx.x;
    int zc = blockIdx.z;
    int b = zc & 7;
    int call = zc >> 3;
    int by = blockIdx.y, bx = blockIdx.x;

    const float* wr = call ? wr1 : wr0;
    const float* wi = call ? wi1 : wi0;

    for (int t = tid; t < COUT*CIN*9; t += 256) {
        int o = t / (CIN*9);
        int i = (t / 9) % CIN;
        int tap = t % 9;
        int dy = tap / 3, dx = tap % 3;
        int widx;
        float sgn;
        if (!ADJ) { widx = ((b*O0 + o)*I0 + i)*9 + dy*3 + dx; sgn = 1.f; }
        else      { widx = ((b*O0 + i)*I0 + o)*9 + dx*3 + dy; sgn = -1.f; }
        float wrv = wr[widx];
        float wiv = sgn * wi[widx];
        swa[t] = make_float2(wrv, wiv);
        swb[t] = make_float2(-wiv, wrv);
    }

    int ib = zc & in_bmask;
    for (int p = 0; p < NPL; p++) {
        int ch   = REALIN ? p : (p >> 1);
        bool im  = REALIN ? false : (p & 1);
        const float* src = (im ? xi : xr) + ib*xbs + ch*xcs;
        for (int idx = tid; idx < 34*34; idx += 256) {
            int r = idx / 34, c = idx % 34;
            int gy = by*32 + r - 1;
            int gxo = bx*32 + c + 3;
            sv[p][idx] = src[(size_t)(gy+1)*Z_W + gxo];
        }
    }
    __syncthreads();

    int tx = threadIdx.x;
    int r0 = threadIdx.y * 4;

    unsigned long long acc2[COUT][4];
    #pragma unroll
    for (int o = 0; o < COUT; o++)
        #pragma unroll
        for (int p = 0; p < 4; p++) acc2[o][p] = 0ull;

    #pragma unroll
    for (int i = 0; i < CIN; i++) {
        float vr[6][3], vi[6][3];
        #pragma unroll
        for (int ry = 0; ry < 6; ry++)
            #pragma unroll
            for (int cx = 0; cx < 3; cx++) {
                int sidx = (r0+ry)*34 + tx + cx;
                if (REALIN) { vr[ry][cx] = sv[i][sidx]; vi[ry][cx] = 0.f; }
                else        { vr[ry][cx] = sv[2*i][sidx]; vi[ry][cx] = sv[2*i+1][sidx]; }
            }
        #pragma unroll
        for (int dy = 0; dy < 3; dy++) {
            #pragma unroll
            for (int dx = 0; dx < 3; dx++) {
                unsigned long long wa[COUT], wb[COUT];
                #pragma unroll
                for (int o = 0; o < COUT; o++) {
                    wa[o] = *(const unsigned long long*)&swa[(o*CIN + i)*9 + dy*3 + dx];
                    if (!REALIN)
                        wb[o] = *(const unsigned long long*)&swb[(o*CIN + i)*9 + dy*3 + dx];
                }
                #pragma unroll
                for (int p = 0; p < 4; p++) {
                    unsigned long long a2 = splat2(vr[p+dy][dx]);
                    unsigned long long c2 = 0ull;
                    if (!REALIN) c2 = splat2(vi[p+dy][dx]);
                    #pragma unroll
                    for (int o = 0; o < COUT; o++) {
                        asm("fma.rn.f32x2 %0, %1, %2, %0;"
                            : "+l"(acc2[o][p]) : "l"(a2), "l"(wa[o]));
                        if (!REALIN)
                            asm("fma.rn.f32x2 %0, %1, %2, %0;"
                                : "+l"(acc2[o][p]) : "l"(c2), "l"(wb[o]));
                    }
                }
            }
        }
    }

    int gx = bx*32 + tx;
    if (gx >= PP_) return;
    #pragma unroll
    for (int p = 0; p < 4; p++) {
        int gy = by*32 + r0 + p;
        if (gy >= PP_) continue;
        size_t doff = (size_t)(gy+1)*Z_W + gx + 4;
        #pragma unroll
        for (int o = 0; o < COUT; o++) {
            float ar, ai;
            asm("mov.b64 {%0, %1}, %2;" : "=f"(ar), "=f"(ai) : "l"(acc2[o][p]));
            if (THETA) {
                const float* tr = call ? tr1 : tr0;
                const float* ti = call ? ti1 : ti0;
                float trv = tr[(size_t)b*PP_*PP_ + gy*PP_ + gx];
                float tiv = ti[(size_t)b*PP_*PP_ + gy*PP_ + gx];
                float nr = ar*trv - ai*tiv;
                float ni = ar*tiv + ai*trv;
                ar = nr; ai = ni;
            }
            yr[(size_t)(zc*4 + o)*PLANE + doff] = ar;
            yi[(size_t)(zc*4 + o)*PLANE + doff] = ai;
        }
    }
}

// x[interior] += coef<1 ? R[call0]/coef : R[call1]*coef
__global__ void update_x_k(float* __restrict__ x, const float* __restrict__ coef)
{
    int idx = blockIdx.x*blockDim.x + threadIdx.x;
    if (idx >= BMM) return;
    int i = idx % MM;
    int j = (idx / MM) % MM;
    int b = idx / MMM;
    float c = coef[idx];
    int ro = b*GDD + j*GD + i;
    float e = (c < 1.f) ? d_R[ro]/c : d_R[8*GDD + ro]*c;
    x[b*NNN + (j+1)*NN_ + (i+1)] += e;
}

// ---------------------------------------------------------------------------
// Final norms
// ---------------------------------------------------------------------------
__global__ void norm_partial_k(const float* __restrict__ f, const float* __restrict__ xin, int nblk)
{
    __shared__ double s1[256], s2[256];
    int tid = threadIdx.x;
    double ar = 0.0, af = 0.0;
    for (int idx = blockIdx.x*blockDim.x + tid; idx < BNN; idx += gridDim.x*blockDim.x) {
        int x = idx % NN_;
        int y = (idx / NN_) % NN_;
        int b = idx / NNN;
        float Ax = 0.f;
        if (y >= 1 && y < NN_-1 && x >= 1 && x < NN_-1)
            Ax = applyA(xin + b*NNN, b, y, x);
        float fv = f[idx];
        float r = fv - Ax;
        ar += (double)r*(double)r;
        af += (double)fv*(double)fv;
    }
    s1[tid] = ar; s2[tid] = af;
    __syncthreads();
    for (int s = 128; s > 0; s >>= 1) {
        if (tid < s) { s1[tid] += s1[tid+s]; s2[tid] += s2[tid+s]; }
        __syncthreads();
    }
    if (tid == 0) { d_part[blockIdx.x] = s1[0]; d_part[nblk + blockIdx.x] = s2[0]; }
}

__global__ void finalize_k(float* __restrict__ out, int nblk)
{
    __shared__ double s1[256], s2[256];
    int tid = threadIdx.x;
    double ar = 0.0, af = 0.0;
    for (int i = tid; i < nblk; i += 256) { ar += d_part[i]; af += d_part[nblk + i]; }
    s1[tid] = ar; s2[tid] = af;
    __syncthreads();
    for (int s = 128; s > 0; s >>= 1) {
        if (tid < s) { s1[tid] += s1[tid+s]; s2[tid] += s2[tid+s]; }
        __syncthreads();
    }
    if (tid == 0) out[0] = (float)sqrt(s1[0] / s2[0]);
}

// ---------------------------------------------------------------------------
// Host launch
// ---------------------------------------------------------------------------
extern "C" void kernel_launch(void* const* d_in, const int* in_sizes, int n_in,
                              void* d_out, int out_size)
{
    const float* f    = (const float*)d_in[0];
    const float* coef = (const float*)d_in[1];
    const float* w11r = (const float*)d_in[2];
    const float* w11i = (const float*)d_in[3];
    const float* w12r = (const float*)d_in[4];
    const float* w12i = (const float*)d_in[5];
    const float* w13r = (const float*)d_in[6];
    const float* w13i = (const float*)d_in[7];
    const float* t1r  = (const float*)d_in[8];
    const float* t1i  = (const float*)d_in[9];
    const float* w21r = (const float*)d_in[10];
    const float* w21i = (const float*)d_in[11];
    const float* w22r = (const float*)d_in[12];
    const float* w22i = (const float*)d_in[13];
    const float* w23r = (const float*)d_in[14];
    const float* w23i = (const float*)d_in[15];
    const float* t2r  = (const float*)d_in[16];
    const float* t2i  = (const float*)d_in[17];
    float* out = (float*)d_out;
    (void)in_sizes; (void)n_in; (void)out_size;

    float *p_x0, *p_x1, *p_r1, *p_T1, *p_rh;
    float *p_Sf, *p_SfT, *p_Ce, *p_Se, *p_CeT, *p_SeT;
    float *p_zar, *p_zai, *p_zbr, *p_zbi;
    float *p_m1, *p_m2, *p_m3, *p_m4, *p_PE, *p_QO, *p_R;
    cudaGetSymbolAddress((void**)&p_x0,  d_x0);
    cudaGetSymbolAddress((void**)&p_x1,  d_x1);
    cudaGetSymbolAddress((void**)&p_r1,  d_r1);
    cudaGetSymbolAddress((void**)&p_T1,  d_T1);
    cudaGetSymbolAddress((void**)&p_rh,  d_rh);
    cudaGetSymbolAddress((void**)&p_Sf,  d_Sf);
    cudaGetSymbolAddress((void**)&p_SfT, d_SfT);
    cudaGetSymbolAddress((void**)&p_Ce,  d_Ce);
    cudaGetSymbolAddress((void**)&p_Se,  d_Se);
    cudaGetSymbolAddress((void**)&p_CeT, d_CeT);
    cudaGetSymbolAddress((void**)&p_SeT, d_SeT);
    cudaGetSymbolAddress((void**)&p_zar, d_zar);
    cudaGetSymbolAddress((void**)&p_zai, d_zai);
    cudaGetSymbolAddress((void**)&p_zbr, d_zbr);
    cudaGetSymbolAddress((void**)&p_zbi, d_zbi);
    cudaGetSymbolAddress((void**)&p_m1,  d_m1);
    cudaGetSymbolAddress((void**)&p_m2,  d_m2);
    cudaGetSymbolAddress((void**)&p_m3,  d_m3);
    cudaGetSymbolAddress((void**)&p_m4,  d_m4);
    cudaGetSymbolAddress((void**)&p_PE,  d_PE);
    cudaGetSymbolAddress((void**)&p_QO,  d_QO);
    cudaGetSymbolAddress((void**)&p_R,   d_R);

    // init
    {
        dim3 b2(16,16), g2((GD+15)/16, (GD+15)/16);
        trig_init_k<<<g2, b2>>>();
    }
    stencil_k<<<(BMM+255)/256, 256>>>(coef);
    r1pad_k<<<BB, 256>>>();
    border_all_k<<<8 + 4*64, 256>>>(p_rh, p_zar, p_zai, p_zbr, p_zbi);

    // 10 Jacobi updates from x=0 (epoch==1 -> K=1): x=w*f then 3 fused 3-sweeps
    const float wrelax = 40.0f / 512.0f;
    first_k<<<(BNN+255)/256, 256>>>(f, p_x0, wrelax);
    {
        dim3 jg(16,16,BB);
        jacobi3_k<<<jg, 256>>>(f, p_x0, p_x1, wrelax);
        jacobi3_k<<<jg, 256>>>(f, p_x1, p_x0, wrelax);
        jacobi3_k<<<jg, 256>>>(f, p_x0, p_x1, wrelax);
    }
    float* xa = p_x1;
    resid_k<<<(BMM+255)/256, 256>>>(f, xa);

    dim3 gg8(4,4,BB);
    // shared forward DST: rh = -(1/511^2) * Sf @ r1 @ SfT
    gemm512_k<<<gg8, 256>>>(p_Sf, 0, GD,  p_r1, GDD, GD,  p_T1, GDD, GD, 1.0f);
    gemm512_k<<<gg8, 256>>>(p_T1, GDD, GD, p_SfT, 0, GD,
                            p_rh + DOFF, (long long)PLANE, Z_W,
                            -1.0f/(511.0f*511.0f));

    // both conv chains, merged over z=16
    dim3 cg(16,16,16), cbk(32,8);
    long long cb_bs = 4LL*PLANE, cb_cs = PLANE;

    conv_k<1,4,false,true ,false><<<cg,cbk>>>(p_rh, nullptr, (long long)PLANE, 0, 7,
        w11r, w11i, w21r, w21i, p_zbr, p_zbi, nullptr,nullptr,nullptr,nullptr, 4, 1);
    conv_k<4,4,false,false,false><<<cg,cbk>>>(p_zbr, p_zbi, cb_bs, cb_cs, 15,
        w12r, w12i, w22r, w22i, p_zar, p_zai, nullptr,nullptr,nullptr,nullptr, 4, 4);
    conv_k<4,1,false,false,true ><<<cg,cbk>>>(p_zar, p_zai, cb_bs, cb_cs, 15,
        w13r, w13i, w23r, w23i, p_zbr, p_zbi, t1r, t1i, t2r, t2i, 1, 4);
    conv_k<1,4,true ,false,false><<<cg,cbk>>>(p_zbr, p_zbi, cb_bs, cb_cs, 15,
        w13r, w13i, w23r, w23i, p_zar, p_zai, nullptr,nullptr,nullptr,nullptr, 1, 4);
    conv_k<4,4,true ,false,false><<<cg,cbk>>>(p_zar, p_zai, cb_bs, cb_cs, 15,
        w12r, w12i, w22r, w22i, p_zbr, p_zbi, nullptr,nullptr,nullptr,nullptr, 4, 4);
    conv_k<4,1,true ,false,false><<<cg,cbk>>>(p_zbr, p_zbi, cb_bs, cb_cs, 15,
        w11r, w11i, w21r, w21i, p_zar, p_zai, nullptr,nullptr,nullptr,nullptr, 4, 1);

    // inverse via parity folding: K=256 GEMMs
    foldz_k<<<(16*FQ + 255)/256, 256>>>(p_zar, p_zai);
    {
        dim3 gq(4,4,64);
        gemm_quad_k<<<gq,256>>>(p_Ce, p_Se, p_m1, p_m2, p_m3, p_m4);
    }
    combine_fold_k<<<(16*GD*KH + 255)/256, 256>>>();
    {
        dim3 gdr(4,4,16);
        gemm_dualR_k<<<gdr,256>>>(p_PE, p_QO, p_CeT, p_SeT, p_R);
    }

    update_x_k<<<(BMM+255)/256, 256>>>(xa, coef);
    const int nblk = 1024;
    norm_partial_k<<<nblk, 256>>>(f, xa, nblk);
    finalize_k<<<1, 256>>>(out, nblk);
}

// round 17
// speedup vs baseline: 1.1926x; 1.1705x over previous
#include <cuda_runtime.h>
#include <math.h>

// ---------------------------------------------------------------------------
// Problem constants
// ---------------------------------------------------------------------------
#define BB   8
#define NN_  512
#define MM   510
#define PP_  511
#define PI_F 3.14159265358979323846f

#define NNN   (NN_*NN_)
#define BNN   (BB*NNN)
#define MMM   (MM*MM)
#define BMM   (BB*MMM)

#define GD    512
#define GDD   (GD*GD)
#define BGDD  (BB*GDD)
#define BG2   (2*BGDD)

#define KH    256               // folded K
#define FQ    (KH*GD)           // one folded quad plane (256x512)

// conv buffer layout: halo'd planes, stride 520, 514 rows, domain at (+1,+4)
#define Z_W   520
#define Z_H   514
#define PLANE (Z_H*Z_W)
#define DOFF  (Z_W + 4)

// ---------------------------------------------------------------------------
// Static device scratch
// ---------------------------------------------------------------------------
__device__ float  d_x0[BNN];
__device__ float  d_x1[BNN];
__device__ float4 d_st4[BMM];
__device__ float d_Sf [GDD];
__device__ float d_SfT[GDD];
__device__ float d_Ce [GD*KH];        // [n, k] cos(pi*k*n/511), rows>=510 zero
__device__ float d_Se [GD*KH];
__device__ float d_CeT[KH*GD];        // [k, n], cols>=510 zero
__device__ float d_SeT[KH*GD];
__device__ float d_r1[BGDD];          // zero-init; pad cells kept zero by r1pad_k
__device__ float d_T1[BGDD];          // forward stage-1 temp
__device__ float d_rh[BB*PLANE];      // shared DST result (real)
__device__ float d_zar[16*4*PLANE];
__device__ float d_zai[16*4*PLANE];
__device__ float d_zbr[16*4*PLANE];
__device__ float d_zbi[16*4*PLANE];
__device__ float d_fold[16*4*FQ];     // per z: aE, bE, aO, bO  (K-major 256x512)
__device__ float d_m1[BG2];           // mA = Ce@aE
__device__ float d_m2[BG2];           // mB = Ce@bE
__device__ float d_m3[BG2];           // mC = Se@aO
__device__ float d_m4[BG2];           // mD = Se@bO
__device__ float d_PE[16*GD*KH];      // folded P, [m, k] lda=256
__device__ float d_QO[16*GD*KH];
__device__ float d_R[BG2];
__device__ double d_part[2*1024];

// ---------------------------------------------------------------------------
// Trig matrices
// ---------------------------------------------------------------------------
__global__ void trig_init_k()
{
    int x = blockIdx.x*blockDim.x + threadIdx.x;
    int y = blockIdx.y*blockDim.y + threadIdx.y;
    if (x >= GD || y >= GD) return;
    float sf = 0.f;
    if (y < PP_ && x < MM) {
        int t = (x+1) * (y-255);
        int m = t % 1022; if (m < 0) m += 1022;
        sf = sinf((float)m * (PI_F/511.0f));
    }
    d_Sf [y*GD + x] = sf;
    d_SfT[x*GD + y] = sf;
    if (x < KH) {
        float c = 0.f, s = 0.f;
        if (y < MM) {
            int m = (x * y) % 1022;
            float ang = (float)m * (PI_F/511.0f);
            c = cosf(ang); s = sinf(ang);
        }
        d_Ce [y*KH + x] = c;
        d_Se [y*KH + x] = s;
        d_CeT[x*GD + y] = c;
        d_SeT[x*GD + y] = s;
    }
}

// ---------------------------------------------------------------------------
// Stencil coefficients (precomputed, float4)
// ---------------------------------------------------------------------------
__global__ void stencil_k(const float* __restrict__ coef)
{
    int idx = blockIdx.x*blockDim.x + threadIdx.x;
    if (idx >= BMM) return;
    int i = idx % MM;
    int j = (idx / MM) % MM;
    int b = idx / MMM;
    const float* cb = coef + b*MMM;
    float a   = cb[j*MM + i];
    float aw  = cb[j*MM + (i>0    ? i-1 : 0   )];
    float ae  = cb[j*MM + (i<MM-1 ? i+1 : MM-1)];
    float an  = cb[(j<MM-1 ? j+1 : MM-1)*MM + i];
    float as_ = cb[(j>0    ? j-1 : 0   )*MM + i];
    float4 s;
    s.x = __fdividef(-2.f*aw *a, aw +a);
    s.y = __fdividef(-2.f*ae *a, ae +a);
    s.z = __fdividef(-2.f*an *a, an +a);
    s.w = __fdividef(-2.f*as_*a, as_+a);
    d_st4[idx] = s;
}

__device__ __forceinline__ float applyA(const float* __restrict__ xb, int b, int y, int x)
{
    int sidx = b*MMM + (y-1)*MM + (x-1);
    float4 s = d_st4[sidx];
    float sc = -(s.x + s.y + s.z + s.w);
    return s.w*xb[(y-1)*NN_+x] + s.x*xb[y*NN_+x-1] + sc*xb[y*NN_+x]
         + s.y*xb[y*NN_+x+1]   + s.z*xb[(y+1)*NN_+x];
}

// zero only the pad cells of r1 (rows/cols >= 510); interior rewritten by resid_k
__global__ void r1pad_k()
{
    int b = blockIdx.x;
    float* p = d_r1 + (size_t)b*GDD;
    for (int t = threadIdx.x; t < 2044; t += 256) {
        int off;
        if (t < 1024) {
            int j = 510 + (t >> 9);
            int i = t & 511;
            off = j*GD + i;
        } else {
            int q = t - 1024;
            int j = q >> 1;
            int i = 510 + (q & 1);
            off = j*GD + i;
        }
        p[off] = 0.f;
    }
}

__global__ void first_k(const float* __restrict__ f, float* __restrict__ xout, float w)
{
    int idx = blockIdx.x*blockDim.x + threadIdx.x;
    if (idx < BNN) xout[idx] = w*f[idx];
}

// zero halo cells of all conv-layout planes in one launch
__global__ void border_all_k(float* __restrict__ rh,
                             float* __restrict__ zar, float* __restrict__ zai,
                             float* __restrict__ zbr, float* __restrict__ zbi)
{
    int zb = blockIdx.x;
    float* pl;
    if (zb < 8) pl = rh + (size_t)zb * PLANE;
    else {
        int q = zb - 8;
        int buf = q >> 6;
        int p  = q & 63;
        float* base = (buf == 0) ? zar : (buf == 1) ? zai : (buf == 2) ? zbr : zbi;
        pl = base + (size_t)p * PLANE;
    }
    const int nA = 3*Z_W;
    const int nB = 511*9;
    for (int i = threadIdx.x; i < nA + nB; i += blockDim.x) {
        int off;
        if (i < nA) {
            int which = i / Z_W;
            int row = (which == 0) ? 0 : (which == 1 ? 512 : 513);
            off = row*Z_W + (i % Z_W);
        } else {
            int j = i - nA;
            int row = 1 + j/9;
            int c9 = j % 9;
            int col = (c9 < 4) ? c9 : (511 + c9);
            off = row*Z_W + col;
        }
        pl[off] = 0.f;
    }
}

// ---------------------------------------------------------------------------
// Fused 3-sweep Jacobi: 38x38 smem tile with shrinking windows 36->34->32.
// ---------------------------------------------------------------------------
__global__ __launch_bounds__(256) void jacobi3_k(
    const float* __restrict__ f, const float* __restrict__ xin,
    float* __restrict__ xout, float w)
{
    __shared__ float xs[2][38][39];
    __shared__ float fs[38][39];
    int tid = threadIdx.x;
    int gx0 = blockIdx.x*32 - 3;
    int gy0 = blockIdx.y*32 - 3;
    int b = blockIdx.z;
    const float* xb = xin + (size_t)b*NNN;
    const float* fb = f   + (size_t)b*NNN;

    for (int i = tid; i < 38*38; i += 256) {
        int ly = i / 38, lx = i % 38;
        int gy = gy0 + ly, gx = gx0 + lx;
        bool in = (gy >= 0 && gy < NN_ && gx >= 0 && gx < NN_);
        xs[0][ly][lx] = in ? xb[gy*NN_ + gx] : 0.f;
        fs[ly][lx]    = in ? fb[gy*NN_ + gx] : 0.f;
    }
    __syncthreads();

    int cur = 0;
    #pragma unroll
    for (int s = 0; s < 3; s++) {
        int m = s + 1;
        int W = 38 - 2*m;
        for (int i = tid; i < W*W; i += 256) {
            int ly = m + i / W, lx = m + i % W;
            int gy = gy0 + ly, gx = gx0 + lx;
            float xv = xs[cur][ly][lx];
            float out;
            if (gy < 0 || gy >= NN_ || gx < 0 || gx >= NN_) {
                out = 0.f;
            } else if (gy >= 1 && gy < NN_-1 && gx >= 1 && gx < NN_-1) {
                float4 st = d_st4[b*MMM + (gy-1)*MM + (gx-1)];
                float sc = -(st.x + st.y + st.z + st.w);
                float Ax = st.w*xs[cur][ly-1][lx] + st.x*xs[cur][ly][lx-1]
                         + sc*xv + st.y*xs[cur][ly][lx+1] + st.z*xs[cur][ly+1][lx];
                out = xv + w*(fs[ly][lx] - Ax);
            } else {
                out = xv + w*fs[ly][lx];
            }
            xs[cur^1][ly][lx] = out;
        }
        __syncthreads();
        cur ^= 1;
    }

    for (int i = tid; i < 32*32; i += 256) {
        int ly = 3 + i / 32, lx = 3 + i % 32;
        int gy = gy0 + ly, gx = gx0 + lx;
        xout[(size_t)b*NNN + gy*NN_ + gx] = xs[cur][ly][lx];
    }
}

__global__ void resid_k(const float* __restrict__ f, const float* __restrict__ xin)
{
    int idx = blockIdx.x*blockDim.x + threadIdx.x;
    if (idx >= BMM) return;
    int i = idx % MM;
    int j = (idx / MM) % MM;
    int b = idx / MMM;
    int y = j+1, x = i+1;
    d_r1[b*GDD + j*GD + i] = f[b*NNN + y*NN_ + x] - applyA(xin + b*NNN, b, y, x);
}

// ---------------------------------------------------------------------------
// helpers for packed f32x2
// ---------------------------------------------------------------------------
__device__ __forceinline__ unsigned long long splat2(float v)
{
    unsigned long long r;
    asm("mov.b64 %0, {%1, %1};" : "=l"(r) : "f"(v));
    return r;
}
__device__ __forceinline__ void fma2(unsigned long long& acc,
                                     unsigned long long a, unsigned long long b)
{
    asm("fma.rn.f32x2 %0, %1, %2, %0;" : "+l"(acc) : "l"(a), "l"(b));
}

// ---------------------------------------------------------------------------
// 512^3 SGEMM, 128x128x8 tile, 8x8 microtile, scalar-A + reg splat (proven core)
// ---------------------------------------------------------------------------
__global__ __launch_bounds__(256, 2) void gemm512_k(
    const float* __restrict__ A, long long sA, int lda,
    const float* __restrict__ Bm, long long sB, int ldb,
    float* __restrict__ C, long long sC, int ldc,
    float alpha)
{
    const float* Ab = A  + blockIdx.z*sA;
    const float* Bb = Bm + blockIdx.z*sB;
    float*       Cb = C  + blockIdx.z*sC;
    __shared__ float As[8][132];
    __shared__ float Bs[8][128];
    int tid = threadIdx.x;
    int arow = tid >> 1;
    int acol = (tid & 1) << 2;
    int brow = tid >> 5;
    int bcol = (tid & 31) << 2;
    const int m0 = blockIdx.y * 128;
    const int n0 = blockIdx.x * 128;
    int row = (tid >> 4) << 3;
    int col = (tid & 15) << 3;

    unsigned long long acc[8][4];
    #pragma unroll
    for (int i = 0; i < 8; i++)
        #pragma unroll
        for (int j = 0; j < 4; j++) acc[i][j] = 0ull;

    const float* Aptr = Ab + (size_t)(m0+arow)*lda + acol;
    const float* Bptr = Bb + (size_t)brow*ldb + n0 + bcol;

    float4 av4 = *(const float4*)(Aptr);
    float4 bv4 = *(const float4*)(Bptr);

    for (int k0 = 0; k0 < 512; k0 += 8) {
        As[acol+0][arow] = av4.x;
        As[acol+1][arow] = av4.y;
        As[acol+2][arow] = av4.z;
        As[acol+3][arow] = av4.w;
        *(float4*)&Bs[brow][bcol] = bv4;
        __syncthreads();
        if (k0 + 8 < 512) {
            av4 = *(const float4*)(Aptr + (k0 + 8));
            bv4 = *(const float4*)(Bptr + (size_t)(k0 + 8)*ldb);
        }
        #pragma unroll
        for (int k = 0; k < 8; k++) {
            float a_[8];
            #pragma unroll
            for (int i = 0; i < 4; i++) {
                float2 t = *(const float2*)&As[k][row + 2*i];
                a_[2*i] = t.x; a_[2*i+1] = t.y;
            }
            unsigned long long b2[4];
            #pragma unroll
            for (int j = 0; j < 4; j++)
                b2[j] = *(const unsigned long long*)&Bs[k][col + 2*j];
            #pragma unroll
            for (int i = 0; i < 8; i++) {
                unsigned long long a2 = splat2(a_[i]);
                #pragma unroll
                for (int j = 0; j < 4; j++)
                    fma2(acc[i][j], a2, b2[j]);
            }
        }
        __syncthreads();
    }
    #pragma unroll
    for (int i = 0; i < 8; i++) {
        float* crow = Cb + (size_t)(m0+row+i)*ldc + n0 + col;
        #pragma unroll
        for (int j = 0; j < 4; j++) {
            float lo, hi;
            asm("mov.b64 {%0, %1}, %2;" : "=f"(lo), "=f"(hi) : "l"(acc[i][j]));
            float2 o; o.x = alpha*lo; o.y = alpha*hi;
            *(float2*)&crow[2*j] = o;
        }
    }
}

// ---------------------------------------------------------------------------
// Fold kernel: from z ch0 (a=Re, b=Im) build aE,bE,aO,bO (K=256 x 512), z=16
// ---------------------------------------------------------------------------
__global__ void foldz_k(const float* __restrict__ zr, const float* __restrict__ zi)
{
    int idx = blockIdx.x*blockDim.x + threadIdx.x;
    if (idx >= 16*FQ) return;
    int v  = idx % GD;
    int k  = (idx / GD) % KH;
    int zc = idx / FQ;
    const float* pa = zr + (size_t)zc*4*PLANE + DOFF;
    const float* pb = zi + (size_t)zc*4*PLANE + DOFF;
    float aE, bE, aO, bO;
    float ap = pa[(size_t)(255+k)*Z_W + v];
    float bp = pb[(size_t)(255+k)*Z_W + v];
    if (k == 0) {
        aE = ap; bE = bp; aO = 0.f; bO = 0.f;
    } else {
        float am = pa[(size_t)(255-k)*Z_W + v];
        float bm = pb[(size_t)(255-k)*Z_W + v];
        aE = ap + am; bE = bp + bm;
        aO = ap - am; bO = bp - bm;
    }
    size_t base = (size_t)zc*4*FQ + (size_t)k*GD + v;
    d_fold[base + 0*FQ] = aE;
    d_fold[base + 1*FQ] = bE;
    d_fold[base + 2*FQ] = aO;
    d_fold[base + 3*FQ] = bO;
}

// ---------------------------------------------------------------------------
// Quad GEMM (K=256): z in [0,64). sel = z>>4:
//   0: mA = Ce@aE   1: mB = Ce@bE   2: mC = Se@aO   3: mD = Se@bO
// ---------------------------------------------------------------------------
__global__ __launch_bounds__(256, 2) void gemm_quad_k(
    const float* __restrict__ Ce, const float* __restrict__ Se,
    float* __restrict__ m1, float* __restrict__ m2,
    float* __restrict__ m3, float* __restrict__ m4)
{
    int zz = blockIdx.z;
    int sel = zz >> 4;
    int zc  = zz & 15;
    const float* Ab = (sel < 2) ? Ce : Se;                     // lda = KH
    const float* Bb = d_fold + (size_t)(zc*4 + sel)*FQ;        // ldb = GD
    float* Cb = ((sel==0)?m1:(sel==1)?m2:(sel==2)?m3:m4) + (size_t)zc*GDD;

    __shared__ float As[8][132];
    __shared__ float Bs[8][128];
    int tid = threadIdx.x;
    int arow = tid >> 1;
    int acol = (tid & 1) << 2;
    int brow = tid >> 5;
    int bcol = (tid & 31) << 2;
    const int m0 = blockIdx.y * 128;
    const int n0 = blockIdx.x * 128;
    int row = (tid >> 4) << 3;
    int col = (tid & 15) << 3;

    unsigned long long acc[8][4];
    #pragma unroll
    for (int i = 0; i < 8; i++)
        #pragma unroll
        for (int j = 0; j < 4; j++) acc[i][j] = 0ull;

    const float* Aptr = Ab + (size_t)(m0+arow)*KH + acol;
    const float* Bptr = Bb + (size_t)brow*GD + n0 + bcol;

    float4 av4 = *(const float4*)(Aptr);
    float4 bv4 = *(const float4*)(Bptr);

    for (int k0 = 0; k0 < KH; k0 += 8) {
        As[acol+0][arow] = av4.x;
        As[acol+1][arow] = av4.y;
        As[acol+2][arow] = av4.z;
        As[acol+3][arow] = av4.w;
        *(float4*)&Bs[brow][bcol] = bv4;
        __syncthreads();
        if (k0 + 8 < KH) {
            av4 = *(const float4*)(Aptr + (k0 + 8));
            bv4 = *(const float4*)(Bptr + (size_t)(k0 + 8)*GD);
        }
        #pragma unroll
        for (int k = 0; k < 8; k++) {
            float a_[8];
            #pragma unroll
            for (int i = 0; i < 4; i++) {
                float2 t = *(const float2*)&As[k][row + 2*i];
                a_[2*i] = t.x; a_[2*i+1] = t.y;
            }
            unsigned long long b2[4];
            #pragma unroll
            for (int j = 0; j < 4; j++)
                b2[j] = *(const unsigned long long*)&Bs[k][col + 2*j];
            #pragma unroll
            for (int i = 0; i < 8; i++) {
                unsigned long long a2 = splat2(a_[i]);
                #pragma unroll
                for (int j = 0; j < 4; j++)
                    fma2(acc[i][j], a2, b2[j]);
            }
        }
        __syncthreads();
    }
    #pragma unroll
    for (int i = 0; i < 8; i++) {
        float* crow = Cb + (size_t)(m0+row+i)*GD + n0 + col;
        #pragma unroll
        for (int j = 0; j < 4; j++) {
            float lo, hi;
            asm("mov.b64 {%0, %1}, %2;" : "=f"(lo), "=f"(hi) : "l"(acc[i][j]));
            float2 o; o.x = lo; o.y = hi;
            *(float2*)&crow[2*j] = o;
        }
    }
}

// ---------------------------------------------------------------------------
// Combine + fold: P = mA+mD, Q = mB-mC; fold columns around 255.
// ---------------------------------------------------------------------------
__global__ void combine_fold_k()
{
    int idx = blockIdx.x*blockDim.x + threadIdx.x;
    if (idx >= 16*GD*KH) return;
    int k  = idx % KH;
    int m  = (idx / KH) % GD;
    int zc = idx / (GD*KH);
    size_t base = (size_t)zc*GDD + (size_t)m*GD;
    float PE, QO;
    float Pp = d_m1[base + 255 + k] + d_m4[base + 255 + k];
    if (k == 0) {
        PE = Pp;
        QO = 0.f;
    } else {
        float Pm = d_m1[base + 255 - k] + d_m4[base + 255 - k];
        PE = Pp + Pm;
        float Qp = d_m2[base + 255 + k] - d_m3[base + 255 + k];
        float Qm = d_m2[base + 255 - k] - d_m3[base + 255 - k];
        QO = Qp - Qm;
    }
    size_t o = (size_t)zc*GD*KH + (size_t)m*KH + k;
    d_PE[o] = PE;
    d_QO[o] = QO;
}

// ---------------------------------------------------------------------------
// Dual GEMM (K=256): R = PE@CeT + QO@SeT, z=16
// ---------------------------------------------------------------------------
__global__ __launch_bounds__(256, 2) void gemm_dualR_k(
    const float* __restrict__ PEm, const float* __restrict__ QOm,
    const float* __restrict__ B1, const float* __restrict__ B2,
    float* __restrict__ R)
{
    int zc = blockIdx.z;
    const float* Pb = PEm + (size_t)zc*GD*KH;
    const float* Qb = QOm + (size_t)zc*GD*KH;
    float* Cb = R + (size_t)zc*GDD;

    __shared__ float Ps[8][132];
    __shared__ float Qs[8][132];
    __shared__ float B1s[8][128];
    __shared__ float B2s[8][128];
    int tid = threadIdx.x;
    int arow = tid >> 1;
    int acol = (tid & 1) << 2;
    int brow = tid >> 5;
    int bcol = (tid & 31) << 2;
    const int m0 = blockIdx.y * 128;
    const int n0 = blockIdx.x * 128;
    int row = (tid >> 4) << 3;
    int col = (tid & 15) << 3;

    unsigned long long acc[8][4];
    #pragma unroll
    for (int i = 0; i < 8; i++)
        #pragma unroll
        for (int j = 0; j < 4; j++) acc[i][j] = 0ull;

    const float* Pptr = Pb + (size_t)(m0+arow)*KH + acol;
    const float* Qptr = Qb + (size_t)(m0+arow)*KH + acol;
    const float* B1p  = B1 + (size_t)brow*GD + n0 + bcol;
    const float* B2p  = B2 + (size_t)brow*GD + n0 + bcol;

    float4 pv  = *(const float4*)(Pptr);
    float4 qv  = *(const float4*)(Qptr);
    float4 b1v = *(const float4*)(B1p);
    float4 b2v = *(const float4*)(B2p);

    for (int k0 = 0; k0 < KH; k0 += 8) {
        Ps[acol+0][arow] = pv.x; Ps[acol+1][arow] = pv.y;
        Ps[acol+2][arow] = pv.z; Ps[acol+3][arow] = pv.w;
        Qs[acol+0][arow] = qv.x; Qs[acol+1][arow] = qv.y;
        Qs[acol+2][arow] = qv.z; Qs[acol+3][arow] = qv.w;
        *(float4*)&B1s[brow][bcol] = b1v;
        *(float4*)&B2s[brow][bcol] = b2v;
        __syncthreads();
        if (k0 + 8 < KH) {
            pv  = *(const float4*)(Pptr + (k0 + 8));
            qv  = *(const float4*)(Qptr + (k0 + 8));
            b1v = *(const float4*)(B1p + (size_t)(k0 + 8)*GD);
            b2v = *(const float4*)(B2p + (size_t)(k0 + 8)*GD);
        }
        #pragma unroll
        for (int k = 0; k < 8; k++) {
            float ap[8], aq[8];
            #pragma unroll
            for (int i = 0; i < 4; i++) {
                float2 t1 = *(const float2*)&Ps[k][row + 2*i];
                float2 t2 = *(const float2*)&Qs[k][row + 2*i];
                ap[2*i] = t1.x; ap[2*i+1] = t1.y;
                aq[2*i] = t2.x; aq[2*i+1] = t2.y;
            }
            unsigned long long c2[4], s2[4];
            #pragma unroll
            for (int j = 0; j < 4; j++) {
                c2[j] = *(const unsigned long long*)&B1s[k][col + 2*j];
                s2[j] = *(const unsigned long long*)&B2s[k][col + 2*j];
            }
            #pragma unroll
            for (int i = 0; i < 8; i++) {
                unsigned long long a2p = splat2(ap[i]);
                unsigned long long a2q = splat2(aq[i]);
                #pragma unroll
                for (int j = 0; j < 4; j++) {
                    fma2(acc[i][j], a2p, c2[j]);
                    fma2(acc[i][j], a2q, s2[j]);
                }
            }
        }
        __syncthreads();
    }
    #pragma unroll
    for (int i = 0; i < 8; i++) {
        float* crow = Cb + (size_t)(m0+row+i)*GD + n0 + col;
        #pragma unroll
        for (int j = 0; j < 4; j++) {
            float lo, hi;
            asm("mov.b64 {%0, %1}, %2;" : "=f"(lo), "=f"(hi) : "l"(acc[i][j]));
            float2 o; o.x = lo; o.y = hi;
            *(float2*)&crow[2*j] = o;
        }
    }
}

// ---------------------------------------------------------------------------
// Tiled complex 3x3 conv (stages 3 and 4 use this; unchanged proven kernel)
// ---------------------------------------------------------------------------
template<int CIN, int COUT, bool ADJ, bool REALIN, bool THETA>
__global__ __launch_bounds__(256) void conv_k(
    const float* __restrict__ xr, const float* __restrict__ xi,
    long long xbs, long long xcs, int in_bmask,
    const float* __restrict__ wr0, const float* __restrict__ wi0,
    const float* __restrict__ wr1, const float* __restrict__ wi1,
    float* __restrict__ yr, float* __restrict__ yi,
    const float* __restrict__ tr0, const float* __restrict__ ti0,
    const float* __restrict__ tr1, const float* __restrict__ ti1,
    int O0, int I0)
{
    const int NPL = CIN * (REALIN ? 1 : 2);
    __shared__ float sv[CIN*(REALIN?1:2)][34*34];
    __shared__ float2 swa[COUT*CIN*9];
    __shared__ float2 swb[COUT*CIN*9];

    int tid = threadIdx.y*32 + threadIdx.x;
    int zc = blockIdx.z;
    int b = zc & 7;
    int call = zc >> 3;
    int by = blockIdx.y, bx = blockIdx.x;

    const float* wr = call ? wr1 : wr0;
    const float* wi = call ? wi1 : wi0;

    for (int t = tid; t < COUT*CIN*9; t += 256) {
        int o = t / (CIN*9);
        int i = (t / 9) % CIN;
        int tap = t % 9;
        int dy = tap / 3, dx = tap % 3;
        int widx;
        float sgn;
        if (!ADJ) { widx = ((b*O0 + o)*I0 + i)*9 + dy*3 + dx; sgn = 1.f; }
        else      { widx = ((b*O0 + i)*I0 + o)*9 + dx*3 + dy; sgn = -1.f; }
        float wrv = wr[widx];
        float wiv = sgn * wi[widx];
        swa[t] = make_float2(wrv, wiv);
        swb[t] = make_float2(-wiv, wrv);
    }

    int ib = zc & in_bmask;
    for (int p = 0; p < NPL; p++) {
        int ch   = REALIN ? p : (p >> 1);
        bool im  = REALIN ? false : (p & 1);
        const float* src = (im ? xi : xr) + ib*xbs + ch*xcs;
        for (int idx = tid; idx < 34*34; idx += 256) {
            int r = idx / 34, c = idx % 34;
            int gy = by*32 + r - 1;
            int gxo = bx*32 + c + 3;
            sv[p][idx] = src[(size_t)(gy+1)*Z_W + gxo];
        }
    }
    __syncthreads();

    int tx = threadIdx.x;
    int r0 = threadIdx.y * 4;

    unsigned long long acc2[COUT][4];
    #pragma unroll
    for (int o = 0; o < COUT; o++)
        #pragma unroll
        for (int p = 0; p < 4; p++) acc2[o][p] = 0ull;

    #pragma unroll
    for (int i = 0; i < CIN; i++) {
        float vr[6][3], vi[6][3];
        #pragma unroll
        for (int ry = 0; ry < 6; ry++)
            #pragma unroll
            for (int cx = 0; cx < 3; cx++) {
                int sidx = (r0+ry)*34 + tx + cx;
                if (REALIN) { vr[ry][cx] = sv[i][sidx]; vi[ry][cx] = 0.f; }
                else        { vr[ry][cx] = sv[2*i][sidx]; vi[ry][cx] = sv[2*i+1][sidx]; }
            }
        #pragma unroll
        for (int dy = 0; dy < 3; dy++) {
            #pragma unroll
            for (int dx = 0; dx < 3; dx++) {
                unsigned long long wa[COUT], wb[COUT];
                #pragma unroll
                for (int o = 0; o < COUT; o++) {
                    wa[o] = *(const unsigned long long*)&swa[(o*CIN + i)*9 + dy*3 + dx];
                    if (!REALIN)
                        wb[o] = *(const unsigned long long*)&swb[(o*CIN + i)*9 + dy*3 + dx];
                }
                #pragma unroll
                for (int p = 0; p < 4; p++) {
                    unsigned long long a2 = splat2(vr[p+dy][dx]);
                    unsigned long long c2 = 0ull;
                    if (!REALIN) c2 = splat2(vi[p+dy][dx]);
                    #pragma unroll
                    for (int o = 0; o < COUT; o++) {
                        fma2(acc2[o][p], a2, wa[o]);
                        if (!REALIN) fma2(acc2[o][p], c2, wb[o]);
                    }
                }
            }
        }
    }

    int gx = bx*32 + tx;
    if (gx >= PP_) return;
    #pragma unroll
    for (int p = 0; p < 4; p++) {
        int gy = by*32 + r0 + p;
        if (gy >= PP_) continue;
        size_t doff = (size_t)(gy+1)*Z_W + gx + 4;
        #pragma unroll
        for (int o = 0; o < COUT; o++) {
            float ar, ai;
            asm("mov.b64 {%0, %1}, %2;" : "=f"(ar), "=f"(ai) : "l"(acc2[o][p]));
            if (THETA) {
                const float* tr = call ? tr1 : tr0;
                const float* ti = call ? ti1 : ti0;
                float trv = tr[(size_t)b*PP_*PP_ + gy*PP_ + gx];
                float tiv = ti[(size_t)b*PP_*PP_ + gy*PP_ + gx];
                float nr = ar*trv - ai*tiv;
                float ni = ar*tiv + ai*trv;
                ar = nr; ai = ni;
            }
            yr[(size_t)(zc*4 + o)*PLANE + doff] = ar;
            yi[(size_t)(zc*4 + o)*PLANE + doff] = ai;
        }
    }
}

// ---------------------------------------------------------------------------
// Fused conv stages 1+2: (1->4 real fwd) on 34x34 mid tile, then (4->4 fwd).
// ---------------------------------------------------------------------------
__global__ __launch_bounds__(256, 2) void conv12_k(
    const float* __restrict__ rh,
    const float* __restrict__ w1r0, const float* __restrict__ w1i0,
    const float* __restrict__ w1r1, const float* __restrict__ w1i1,
    const float* __restrict__ w2r0, const float* __restrict__ w2i0,
    const float* __restrict__ w2r1, const float* __restrict__ w2i1,
    float* __restrict__ yr, float* __restrict__ yi)
{
    __shared__ float sv[36*37];
    __shared__ float midR[4][34*35];
    __shared__ float midI[4][34*35];
    __shared__ float2 sw1[4*9];
    __shared__ float2 swa2[4*4*9];
    __shared__ float2 swb2[4*4*9];

    int tid = threadIdx.y*32 + threadIdx.x;
    int zc = blockIdx.z;
    int b = zc & 7;
    int call = zc >> 3;
    int by = blockIdx.y, bx = blockIdx.x;

    const float* w1r = call ? w1r1 : w1r0;
    const float* w1i = call ? w1i1 : w1i0;
    const float* w2r = call ? w2r1 : w2r0;
    const float* w2i = call ? w2i1 : w2i0;

    for (int t = tid; t < 36; t += 256)
        sw1[t] = make_float2(w1r[(b*4 + t/9)*9 + t%9], w1i[(b*4 + t/9)*9 + t%9]);
    for (int t = tid; t < 144; t += 256) {
        int o = t / 36, i = (t/9) % 4, tap = t % 9;
        float wrv = w2r[((b*4+o)*4 + i)*9 + tap];
        float wiv = w2i[((b*4+o)*4 + i)*9 + tap];
        swa2[t] = make_float2(wrv, wiv);
        swb2[t] = make_float2(-wiv, wrv);
    }

    const float* src = rh + (size_t)b*PLANE;
    int gy0 = by*32 - 2, gx0 = bx*32 - 2;
    for (int t = tid; t < 36*36; t += 256) {
        int r = t / 36, c = t % 36;
        int row = gy0 + r + 1;
        int col = gx0 + c + 4;
        sv[r*37 + c] = (row >= 0 && row < Z_H) ? src[(size_t)row*Z_W + col] : 0.f;
    }
    __syncthreads();

    for (int t = tid; t < 34*34; t += 256) {
        int my = t / 34, mx = t % 34;
        int gy = by*32 - 1 + my, gx = bx*32 - 1 + mx;
        unsigned long long acc[4] = {0ull, 0ull, 0ull, 0ull};
        if (gy >= 0 && gy < PP_ && gx >= 0 && gx < PP_) {
            #pragma unroll
            for (int dy = 0; dy < 3; dy++)
                #pragma unroll
                for (int dx = 0; dx < 3; dx++) {
                    unsigned long long a2 = splat2(sv[(my+dy)*37 + mx+dx]);
                    #pragma unroll
                    for (int o = 0; o < 4; o++) {
                        unsigned long long w = *(const unsigned long long*)&sw1[o*9 + dy*3 + dx];
                        fma2(acc[o], a2, w);
                    }
                }
        }
        #pragma unroll
        for (int o = 0; o < 4; o++) {
            float rr, ii;
            asm("mov.b64 {%0, %1}, %2;" : "=f"(rr), "=f"(ii) : "l"(acc[o]));
            midR[o][my*35 + mx] = rr;
            midI[o][my*35 + mx] = ii;
        }
    }
    __syncthreads();

    int tx = threadIdx.x;
    int r0 = threadIdx.y * 4;
    unsigned long long acc2[4][4];
    #pragma unroll
    for (int o = 0; o < 4; o++)
        #pragma unroll
        for (int p = 0; p < 4; p++) acc2[o][p] = 0ull;

    #pragma unroll
    for (int i = 0; i < 4; i++) {
        float vr[6][3], vi[6][3];
        #pragma unroll
        for (int ry = 0; ry < 6; ry++)
            #pragma unroll
            for (int cx = 0; cx < 3; cx++) {
                int sidx = (r0+ry)*35 + tx + cx;
                vr[ry][cx] = midR[i][sidx];
                vi[ry][cx] = midI[i][sidx];
            }
        #pragma unroll
        for (int dy = 0; dy < 3; dy++)
            #pragma unroll
            for (int dx = 0; dx < 3; dx++) {
                unsigned long long wa[4], wb[4];
                #pragma unroll
                for (int o = 0; o < 4; o++) {
                    wa[o] = *(const unsigned long long*)&swa2[(o*4 + i)*9 + dy*3 + dx];
                    wb[o] = *(const unsigned long long*)&swb2[(o*4 + i)*9 + dy*3 + dx];
                }
                #pragma unroll
                for (int p = 0; p < 4; p++) {
                    unsigned long long a2 = splat2(vr[p+dy][dx]);
                    unsigned long long c2 = splat2(vi[p+dy][dx]);
                    #pragma unroll
                    for (int o = 0; o < 4; o++) {
                        fma2(acc2[o][p], a2, wa[o]);
                        fma2(acc2[o][p], c2, wb[o]);
                    }
                }
            }
    }

    int gx = bx*32 + tx;
    if (gx >= PP_) return;
    #pragma unroll
    for (int p = 0; p < 4; p++) {
        int gy = by*32 + r0 + p;
        if (gy >= PP_) continue;
        size_t doff = (size_t)(gy+1)*Z_W + gx + 4;
        #pragma unroll
        for (int o = 0; o < 4; o++) {
            float ar, ai;
            asm("mov.b64 {%0, %1}, %2;" : "=f"(ar), "=f"(ai) : "l"(acc2[o][p]));
            yr[(size_t)(zc*4 + o)*PLANE + doff] = ar;
            yi[(size_t)(zc*4 + o)*PLANE + doff] = ai;
        }
    }
}

// ---------------------------------------------------------------------------
// Fused conv stages 5+6: (4->4 adj) on 34x34 mid tile, then (4->1 adj).
// ---------------------------------------------------------------------------
__global__ __launch_bounds__(256, 2) void conv56_k(
    const float* __restrict__ xr, const float* __restrict__ xi,
    const float* __restrict__ w2r0, const float* __restrict__ w2i0,
    const float* __restrict__ w2r1, const float* __restrict__ w2i1,
    const float* __restrict__ w1r0, const float* __restrict__ w1i0,
    const float* __restrict__ w1r1, const float* __restrict__ w1i1,
    float* __restrict__ yr, float* __restrict__ yi)
{
    __shared__ float sbuf[8*1332];
    __shared__ float2 swa5[144];
    __shared__ float2 swb5[144];
    __shared__ float2 swa6[36];
    __shared__ float2 swb6[36];

    int tid = threadIdx.y*32 + threadIdx.x;
    int zc = blockIdx.z;
    int b = zc & 7;
    int call = zc >> 3;
    int by = blockIdx.y, bx = blockIdx.x;

    const float* w2r = call ? w2r1 : w2r0;
    const float* w2i = call ? w2i1 : w2i0;
    const float* w1r = call ? w1r1 : w1r0;
    const float* w1i = call ? w1i1 : w1i0;

    for (int t = tid; t < 144; t += 256) {
        int o = t / 36, i = (t/9) % 4, tap = t % 9;
        int dy = tap / 3, dx = tap % 3;
        float wrv =  w2r[((b*4+i)*4 + o)*9 + dx*3 + dy];
        float wiv = -w2i[((b*4+i)*4 + o)*9 + dx*3 + dy];
        swa5[t] = make_float2(wrv, wiv);
        swb5[t] = make_float2(-wiv, wrv);
    }
    for (int t = tid; t < 36; t += 256) {
        int i = t / 9, tap = t % 9;
        int dy = tap / 3, dx = tap % 3;
        float wrv =  w1r[(b*4+i)*9 + dx*3 + dy];
        float wiv = -w1i[(b*4+i)*9 + dx*3 + dy];
        swa6[t] = make_float2(wrv, wiv);
        swb6[t] = make_float2(-wiv, wrv);
    }

    int gy0 = by*32 - 2, gx0 = bx*32 - 2;
    for (int p = 0; p < 8; p++) {
        int ch = p >> 1;
        const float* src = ((p & 1) ? xi : xr) + ((size_t)zc*4 + ch)*PLANE;
        for (int t = tid; t < 36*36; t += 256) {
            int r = t / 36, c = t % 36;
            int row = gy0 + r + 1;
            int col = gx0 + c + 4;
            sbuf[p*1332 + r*37 + c] =
                (row >= 0 && row < Z_H) ? src[(size_t)row*Z_W + col] : 0.f;
        }
    }
    __syncthreads();

    int colm = tid % 34;
    int rowg = tid / 34;
    int r0m = rowg * 5;
    bool activeA = (rowg < 7);
    float aR[5][4], aI[5][4];
    #pragma unroll
    for (int p = 0; p < 5; p++)
        #pragma unroll
        for (int o = 0; o < 4; o++) { aR[p][o] = 0.f; aI[p][o] = 0.f; }

    if (activeA) {
        unsigned long long accA[4][5];
        #pragma unroll
        for (int o = 0; o < 4; o++)
            #pragma unroll
            for (int p = 0; p < 5; p++) accA[o][p] = 0ull;

        #pragma unroll
        for (int i = 0; i < 4; i++) {
            float vr[7][3], vi[7][3];
            #pragma unroll
            for (int ry = 0; ry < 7; ry++)
                #pragma unroll
                for (int cx = 0; cx < 3; cx++) {
                    int rr = r0m + ry;
                    if (rr < 36) {
                        int sidx = rr*37 + colm + cx;
                        vr[ry][cx] = sbuf[(2*i)*1332 + sidx];
                        vi[ry][cx] = sbuf[(2*i+1)*1332 + sidx];
                    } else { vr[ry][cx] = 0.f; vi[ry][cx] = 0.f; }
                }
            #pragma unroll
            for (int dy = 0; dy < 3; dy++)
                #pragma unroll
                for (int dx = 0; dx < 3; dx++) {
                    unsigned long long wa[4], wb[4];
                    #pragma unroll
                    for (int o = 0; o < 4; o++) {
                        wa[o] = *(const unsigned long long*)&swa5[(o*4 + i)*9 + dy*3 + dx];
                        wb[o] = *(const unsigned long long*)&swb5[(o*4 + i)*9 + dy*3 + dx];
                    }
                    #pragma unroll
                    for (int p = 0; p < 5; p++) {
                        unsigned long long a2 = splat2(vr[p+dy][dx]);
                        unsigned long long c2 = splat2(vi[p+dy][dx]);
                        #pragma unroll
                        for (int o = 0; o < 4; o++) {
                            fma2(accA[o][p], a2, wa[o]);
                            fma2(accA[o][p], c2, wb[o]);
                        }
                    }
                }
        }
        #pragma unroll
        for (int p = 0; p < 5; p++) {
            int my = r0m + p;
            int gy = by*32 - 1 + my, gx = bx*32 - 1 + colm;
            bool valid = (my < 34) && (gy >= 0 && gy < PP_ && gx >= 0 && gx < PP_);
            #pragma unroll
            for (int o = 0; o < 4; o++) {
                float rr = 0.f, ii = 0.f;
                if (valid)
                    asm("mov.b64 {%0, %1}, %2;" : "=f"(rr), "=f"(ii) : "l"(accA[o][p]));
                aR[p][o] = rr; aI[p][o] = ii;
            }
        }
    }
    __syncthreads();

    if (activeA) {
        #pragma unroll
        for (int p = 0; p < 5; p++) {
            int my = r0m + p;
            if (my < 34) {
                #pragma unroll
                for (int o = 0; o < 4; o++) {
                    sbuf[(2*o)*1190   + my*35 + colm] = aR[p][o];
                    sbuf[(2*o+1)*1190 + my*35 + colm] = aI[p][o];
                }
            }
        }
    }
    __syncthreads();

    int tx = threadIdx.x;
    int r0 = threadIdx.y * 4;
    unsigned long long acc2[4];
    #pragma unroll
    for (int p = 0; p < 4; p++) acc2[p] = 0ull;

    #pragma unroll
    for (int i = 0; i < 4; i++) {
        float vr[6][3], vi[6][3];
        #pragma unroll
        for (int ry = 0; ry < 6; ry++)
            #pragma unroll
            for (int cx = 0; cx < 3; cx++) {
                int sidx = (r0+ry)*35 + tx + cx;
                vr[ry][cx] = sbuf[(2*i)*1190 + sidx];
                vi[ry][cx] = sbuf[(2*i+1)*1190 + sidx];
            }
        #pragma unroll
        for (int dy = 0; dy < 3; dy++)
            #pragma unroll
            for (int dx = 0; dx < 3; dx++) {
                unsigned long long wa = *(const unsigned long long*)&swa6[i*9 + dy*3 + dx];
                unsigned long long wb = *(const unsigned long long*)&swb6[i*9 + dy*3 + dx];
                #pragma unroll
                for (int p = 0; p < 4; p++) {
                    unsigned long long a2 = splat2(vr[p+dy][dx]);
                    unsigned long long c2 = splat2(vi[p+dy][dx]);
                    fma2(acc2[p], a2, wa);
                    fma2(acc2[p], c2, wb);
                }
            }
    }

    int gx = bx*32 + tx;
    if (gx >= PP_) return;
    #pragma unroll
    for (int p = 0; p < 4; p++) {
        int gy = by*32 + r0 + p;
        if (gy >= PP_) continue;
        size_t doff = (size_t)(gy+1)*Z_W + gx + 4;
        float ar, ai;
        asm("mov.b64 {%0, %1}, %2;" : "=f"(ar), "=f"(ai) : "l"(acc2[p]));
        yr[(size_t)(zc*4)*PLANE + doff] = ar;
        yi[(size_t)(zc*4)*PLANE + doff] = ai;
    }
}

// x[interior] += coef<1 ? R[call0]/coef : R[call1]*coef
__global__ void update_x_k(float* __restrict__ x, const float* __restrict__ coef)
{
    int idx = blockIdx.x*blockDim.x + threadIdx.x;
    if (idx >= BMM) return;
    int i = idx % MM;
    int j = (idx / MM) % MM;
    int b = idx / MMM;
    float c = coef[idx];
    int ro = b*GDD + j*GD + i;
    float e = (c < 1.f) ? d_R[ro]/c : d_R[8*GDD + ro]*c;
    x[b*NNN + (j+1)*NN_ + (i+1)] += e;
}

// ---------------------------------------------------------------------------
// Final norms
// ---------------------------------------------------------------------------
__global__ void norm_partial_k(const float* __restrict__ f, const float* __restrict__ xin, int nblk)
{
    __shared__ double s1[256], s2[256];
    int tid = threadIdx.x;
    double ar = 0.0, af = 0.0;
    for (int idx = blockIdx.x*blockDim.x + tid; idx < BNN; idx += gridDim.x*blockDim.x) {
        int x = idx % NN_;
        int y = (idx / NN_) % NN_;
        int b = idx / NNN;
        float Ax = 0.f;
        if (y >= 1 && y < NN_-1 && x >= 1 && x < NN_-1)
            Ax = applyA(xin + b*NNN, b, y, x);
        float fv = f[idx];
        float r = fv - Ax;
        ar += (double)r*(double)r;
        af += (double)fv*(double)fv;
    }
    s1[tid] = ar; s2[tid] = af;
    __syncthreads();
    for (int s = 128; s > 0; s >>= 1) {
        if (tid < s) { s1[tid] += s1[tid+s]; s2[tid] += s2[tid+s]; }
        __syncthreads();
    }
    if (tid == 0) { d_part[blockIdx.x] = s1[0]; d_part[nblk + blockIdx.x] = s2[0]; }
}

__global__ void finalize_k(float* __restrict__ out, int nblk)
{
    __shared__ double s1[256], s2[256];
    int tid = threadIdx.x;
    double ar = 0.0, af = 0.0;
    for (int i = tid; i < nblk; i += 256) { ar += d_part[i]; af += d_part[nblk + i]; }
    s1[tid] = ar; s2[tid] = af;
    __syncthreads();
    for (int s = 128; s > 0; s >>= 1) {
        if (tid < s) { s1[tid] += s1[tid+s]; s2[tid] += s2[tid+s]; }
        __syncthreads();
    }
    if (tid == 0) out[0] = (float)sqrt(s1[0] / s2[0]);
}

// ---------------------------------------------------------------------------
// Host launch
// ---------------------------------------------------------------------------
extern "C" void kernel_launch(void* const* d_in, const int* in_sizes, int n_in,
                              void* d_out, int out_size)
{
    const float* f    = (const float*)d_in[0];
    const float* coef = (const float*)d_in[1];
    const float* w11r = (const float*)d_in[2];
    const float* w11i = (const float*)d_in[3];
    const float* w12r = (const float*)d_in[4];
    const float* w12i = (const float*)d_in[5];
    const float* w13r = (const float*)d_in[6];
    const float* w13i = (const float*)d_in[7];
    const float* t1r  = (const float*)d_in[8];
    const float* t1i  = (const float*)d_in[9];
    const float* w21r = (const float*)d_in[10];
    const float* w21i = (const float*)d_in[11];
    const float* w22r = (const float*)d_in[12];
    const float* w22i = (const float*)d_in[13];
    const float* w23r = (const float*)d_in[14];
    const float* w23i = (const float*)d_in[15];
    const float* t2r  = (const float*)d_in[16];
    const float* t2i  = (const float*)d_in[17];
    float* out = (float*)d_out;
    (void)in_sizes; (void)n_in; (void)out_size;

    float *p_x0, *p_x1, *p_r1, *p_T1, *p_rh;
    float *p_Sf, *p_SfT, *p_Ce, *p_Se, *p_CeT, *p_SeT;
    float *p_zar, *p_zai, *p_zbr, *p_zbi;
    float *p_m1, *p_m2, *p_m3, *p_m4, *p_PE, *p_QO, *p_R;
    cudaGetSymbolAddress((void**)&p_x0,  d_x0);
    cudaGetSymbolAddress((void**)&p_x1,  d_x1);
    cudaGetSymbolAddress((void**)&p_r1,  d_r1);
    cudaGetSymbolAddress((void**)&p_T1,  d_T1);
    cudaGetSymbolAddress((void**)&p_rh,  d_rh);
    cudaGetSymbolAddress((void**)&p_Sf,  d_Sf);
    cudaGetSymbolAddress((void**)&p_SfT, d_SfT);
    cudaGetSymbolAddress((void**)&p_Ce,  d_Ce);
    cudaGetSymbolAddress((void**)&p_Se,  d_Se);
    cudaGetSymbolAddress((void**)&p_CeT, d_CeT);
    cudaGetSymbolAddress((void**)&p_SeT, d_SeT);
    cudaGetSymbolAddress((void**)&p_zar, d_zar);
    cudaGetSymbolAddress((void**)&p_zai, d_zai);
    cudaGetSymbolAddress((void**)&p_zbr, d_zbr);
    cudaGetSymbolAddress((void**)&p_zbi, d_zbi);
    cudaGetSymbolAddress((void**)&p_m1,  d_m1);
    cudaGetSymbolAddress((void**)&p_m2,  d_m2);
    cudaGetSymbolAddress((void**)&p_m3,  d_m3);
    cudaGetSymbolAddress((void**)&p_m4,  d_m4);
    cudaGetSymbolAddress((void**)&p_PE,  d_PE);
    cudaGetSymbolAddress((void**)&p_QO,  d_QO);
    cudaGetSymbolAddress((void**)&p_R,   d_R);

    // init
    {
        dim3 b2(16,16), g2((GD+15)/16, (GD+15)/16);
        trig_init_k<<<g2, b2>>>();
    }
    stencil_k<<<(BMM+255)/256, 256>>>(coef);
    r1pad_k<<<BB, 256>>>();
    border_all_k<<<8 + 4*64, 256>>>(p_rh, p_zar, p_zai, p_zbr, p_zbi);

    // 10 Jacobi updates from x=0 (epoch==1 -> K=1): x=w*f then 3 fused 3-sweeps
    const float wrelax = 40.0f / 512.0f;
    first_k<<<(BNN+255)/256, 256>>>(f, p_x0, wrelax);
    {
        dim3 jg(16,16,BB);
        jacobi3_k<<<jg, 256>>>(f, p_x0, p_x1, wrelax);
        jacobi3_k<<<jg, 256>>>(f, p_x1, p_x0, wrelax);
        jacobi3_k<<<jg, 256>>>(f, p_x0, p_x1, wrelax);
    }
    float* xa = p_x1;
    resid_k<<<(BMM+255)/256, 256>>>(f, xa);

    dim3 gg8(4,4,BB);
    // shared forward DST: rh = -(1/511^2) * Sf @ r1 @ SfT
    gemm512_k<<<gg8, 256>>>(p_Sf, 0, GD,  p_r1, GDD, GD,  p_T1, GDD, GD, 1.0f);
    gemm512_k<<<gg8, 256>>>(p_T1, GDD, GD, p_SfT, 0, GD,
                            p_rh + DOFF, (long long)PLANE, Z_W,
                            -1.0f/(511.0f*511.0f));

    // conv chain (both calls merged over z=16):
    //   fused 1+2  -> zar/zai
    //   3 + theta  -> zbr/zbi
    //   4 (adj)    -> zar/zai
    //   fused 5+6  -> zbr/zbi (ch0)
    dim3 cg(16,16,16), cbk(32,8);
    long long cb_bs = 4LL*PLANE, cb_cs = PLANE;

    conv12_k<<<cg,cbk>>>(p_rh,
        w11r, w11i, w21r, w21i, w12r, w12i, w22r, w22i,
        p_zar, p_zai);
    conv_k<4,1,false,false,true ><<<cg,cbk>>>(p_zar, p_zai, cb_bs, cb_cs, 15,
        w13r, w13i, w23r, w23i, p_zbr, p_zbi, t1r, t1i, t2r, t2i, 1, 4);
    conv_k<1,4,true ,false,false><<<cg,cbk>>>(p_zbr, p_zbi, cb_bs, cb_cs, 15,
        w13r, w13i, w23r, w23i, p_zar, p_zai, nullptr,nullptr,nullptr,nullptr, 1, 4);
    conv56_k<<<cg,cbk>>>(p_zar, p_zai,
        w12r, w12i, w22r, w22i, w11r, w11i, w21r, w21i,
        p_zbr, p_zbi);

    // inverse via parity folding: K=256 GEMMs (reads stage-6 output in zbr/zbi)
    foldz_k<<<(16*FQ + 255)/256, 256>>>(p_zbr, p_zbi);
    {
        dim3 gq(4,4,64);
        gemm_quad_k<<<gq,256>>>(p_Ce, p_Se, p_m1, p_m2, p_m3, p_m4);
    }
    combine_fold_k<<<(16*GD*KH + 255)/256, 256>>>();
    {
        dim3 gdr(4,4,16);
        gemm_dualR_k<<<gdr,256>>>(p_PE, p_QO, p_CeT, p_SeT, p_R);
    }

    update_x_k<<<(BMM+255)/256, 256>>>(xa, coef);
    const int nblk = 1024;
    norm_partial_k<<<nblk, 256>>>(f, xa, nblk);
    finalize_k<<<1, 256>>>(out, nblk);
}